// round 9
// baseline (speedup 1.0000x reference)
#include <cuda_runtime.h>
#include <math.h>

#define BB 2
#define SS 1024
#define DD 1024
#define HH 16
#define HD 64
#define LL 4
#define FFD 2816
#define VV 32000
#define MROWS (BB*SS)   // 2048
#define EPSV 1e-6f

// ---------------- scratch (device globals; no allocations) ----------------
__device__ float g_h  [MROWS*DD];
__device__ float g_q  [MROWS*DD];
__device__ float g_k  [MROWS*DD];
__device__ float g_v  [MROWS*DD];
__device__ float g_f1 [MROWS*FFD];
__device__ float g_f3 [MROWS*FFD];
__device__ float g_cos[SS*(HD/2)];
__device__ float g_sin[SS*(HD/2)];

// pre-split hi/lo operand buffers
__device__ float g_hn_hi[MROWS*DD],  g_hn_lo[MROWS*DD];
__device__ float g_ao_hi[MROWS*DD],  g_ao_lo[MROWS*DD];
__device__ float g_f1_hi[MROWS*FFD], g_f1_lo[MROWS*FFD];

__device__ float g_wq_hi[LL*DD*DD],  g_wq_lo[LL*DD*DD];
__device__ float g_wk_hi[LL*DD*DD],  g_wk_lo[LL*DD*DD];
__device__ float g_wv_hi[LL*DD*DD],  g_wv_lo[LL*DD*DD];
__device__ float g_wo_hi[LL*DD*DD],  g_wo_lo[LL*DD*DD];
__device__ float g_w1_hi[LL*DD*FFD], g_w1_lo[LL*DD*FFD];
__device__ float g_w3_hi[LL*DD*FFD], g_w3_lo[LL*DD*FFD];
__device__ float g_w2_hi[LL*FFD*DD], g_w2_lo[LL*FFD*DD];
__device__ float g_emb_hi[VV*DD],    g_emb_lo[VV*DD];

// ---------------- tf32 split helpers ----------------
__device__ __forceinline__ unsigned f2tf(float f) {
    unsigned u;
    asm("cvt.rna.tf32.f32 %0, %1;" : "=r"(u) : "f"(f));
    return u;
}
__device__ __forceinline__ float2 split_tf2(float f) {
    unsigned hi = f2tf(f);
    unsigned lo = f2tf(f - __uint_as_float(hi));
    return make_float2(__uint_as_float(hi), __uint_as_float(lo));
}

// split a float array into tf32 hi/lo arrays (vectorized)
__global__ void split4_kernel(const float4* __restrict__ src,
                              float4* __restrict__ hi, float4* __restrict__ lo, int n4) {
    int i = blockIdx.x*blockDim.x + threadIdx.x;
    if (i >= n4) return;
    float4 v = src[i];
    float2 sx = split_tf2(v.x), sy = split_tf2(v.y), sz = split_tf2(v.z), sw = split_tf2(v.w);
    hi[i] = make_float4(sx.x, sy.x, sz.x, sw.x);
    lo[i] = make_float4(sx.y, sy.y, sz.y, sw.y);
}

// ---------------- small elementwise kernels ----------------
__global__ void rope_tables_kernel() {
    int idx = blockIdx.x*blockDim.x + threadIdx.x;
    if (idx >= SS*(HD/2)) return;
    int s = idx / (HD/2);
    int j = idx % (HD/2);
    float inv = powf(10000.0f, -2.0f*(float)j/(float)HD);
    float ang = (float)s * inv;
    g_cos[idx] = cosf(ang);
    g_sin[idx] = sinf(ang);
}

__global__ void embed_kernel(const int* __restrict__ tokens, const float* __restrict__ emb) {
    int idx = blockIdx.x*blockDim.x + threadIdx.x;
    if (idx >= MROWS*DD) return;
    int row = idx / DD;
    int d   = idx % DD;
    g_h[idx] = emb[(size_t)tokens[row]*DD + d];
}

__global__ void rope_kernel(float* __restrict__ x) {
    int idx = blockIdx.x*blockDim.x + threadIdx.x;
    const int total = BB*SS*HH*(HD/2);
    if (idx >= total) return;
    int j = idx % (HD/2);
    int h = (idx/(HD/2)) % HH;
    int s = (idx/(HD/2)/HH) % SS;
    int b =  idx/(HD/2)/HH/SS;
    float c  = g_cos[s*(HD/2)+j];
    float sn = g_sin[s*(HD/2)+j];
    size_t base = (size_t)(b*SS+s)*DD + h*HD + 2*j;
    float x0 = x[base], x1 = x[base+1];
    x[base]   = x0*c - x1*sn;
    x[base+1] = x0*sn + x1*c;
}

// rmsnorm producing pre-split hi/lo output (GEMM A operand)
__global__ void rmsnorm_split_kernel(const float* __restrict__ x, const float* __restrict__ w,
                                     float* __restrict__ out_hi, float* __restrict__ out_lo) {
    int row = blockIdx.x;
    int t   = threadIdx.x;
    const float* xr = x + (size_t)row*DD;
    float v[4];
    float ss = 0.f;
    #pragma unroll
    for (int e = 0; e < 4; e++) { v[e] = xr[t + e*256]; ss += v[e]*v[e]; }
    __shared__ float red[256];
    red[t] = ss; __syncthreads();
    for (int off = 128; off > 0; off >>= 1) {
        if (t < off) red[t] += red[t+off];
        __syncthreads();
    }
    float scale = rsqrtf(red[0]/(float)DD + EPSV);
    #pragma unroll
    for (int e = 0; e < 4; e++) {
        int d = t + e*256;
        float2 s2 = split_tf2(v[e]*scale*w[d]);
        out_hi[(size_t)row*DD + d] = s2.x;
        out_lo[(size_t)row*DD + d] = s2.y;
    }
}

__global__ void silu_mul_kernel() {
    int idx = blockIdx.x*blockDim.x + threadIdx.x;
    if (idx >= MROWS*FFD) return;
    float a = g_f1[idx];
    float sig = 1.0f / (1.0f + __expf(-a));
    float2 s2 = split_tf2(a*sig*g_f3[idx]);
    g_f1_hi[idx] = s2.x;
    g_f1_lo[idx] = s2.y;
}

// ---------------- 3xTF32 GEMM on pre-split operands ----------------
// C[M,N] = A[M,K] @ op(B);  TRANSB=0: B[K,N];  TRANSB=1: B[N,K].
// All operands arrive as separate hi/lo fp32 arrays (values already tf32-exact).
// Block tile 128x128, K-chunk 16, 8 warps 4(m)x2(n), warp tile 32x64, m16n8k8.
// Inner loop: pure LDS.32 + MMA (no cvt/sub).

__device__ __forceinline__ void mma_tf32(float* c, const unsigned* a, const unsigned* b) {
    asm volatile(
        "mma.sync.aligned.m16n8k8.row.col.f32.tf32.tf32.f32 "
        "{%0,%1,%2,%3}, {%4,%5,%6,%7}, {%8,%9}, {%0,%1,%2,%3};\n"
        : "+f"(c[0]), "+f"(c[1]), "+f"(c[2]), "+f"(c[3])
        : "r"(a[0]), "r"(a[1]), "r"(a[2]), "r"(a[3]), "r"(b[0]), "r"(b[1]));
}

#define PADW 136
#define BUFU (16*PADW)                    // floats per 16xPADW tile
#define GEMM_SMEM_BYTES (8*BUFU*4)        // A_hi/A_lo/B_hi/B_lo x double buffer

// stage 128(rows) x 16(k) from row-major src (ld = row stride) into [k][row] tile
__device__ __forceinline__ void stage_rm(const float* __restrict__ src, int ld,
                                         int r0, int k0, float* __restrict__ dst, int tid) {
    #pragma unroll
    for (int e = 0; e < 2; e++) {
        int idx = tid + e*256;
        int row = idx >> 2;
        int kq  = (idx & 3) << 2;
        float4 v = *(const float4*)&src[(size_t)(r0+row)*ld + k0 + kq];
        dst[(kq+0)*PADW + row] = v.x;
        dst[(kq+1)*PADW + row] = v.y;
        dst[(kq+2)*PADW + row] = v.z;
        dst[(kq+3)*PADW + row] = v.w;
    }
}

// stage 16(k) x 128(n) from row-major src[K][N] into [k][n] tile
__device__ __forceinline__ void stage_cm(const float* __restrict__ src, int ld,
                                         int n0, int k0, float* __restrict__ dst, int tid) {
    #pragma unroll
    for (int e = 0; e < 2; e++) {
        int idx = tid + e*256;
        int k  = idx >> 5;
        int nq = (idx & 31) << 2;
        float4 v = *(const float4*)&src[(size_t)(k0+k)*ld + n0 + nq];
        *(float4*)&dst[k*PADW + nq] = v;
    }
}

template<int TRANSB, int ACC>
__global__ void __launch_bounds__(256)
gemm4_kernel(const float* __restrict__ Ah, const float* __restrict__ Al,
             const float* __restrict__ Bh, const float* __restrict__ Bl,
             float* __restrict__ C, int M, int N, int K) {
    extern __shared__ float sm[];
    float* SAh = sm;              // [2][16][PADW]
    float* SAl = sm + 2*BUFU;
    float* SBh = sm + 4*BUFU;
    float* SBl = sm + 6*BUFU;

    int tid  = threadIdx.x;
    int lane = tid & 31;
    int gr   = lane >> 2;     // 0..7
    int tg   = lane & 3;      // 0..3
    int wid  = tid >> 5;      // 0..7
    int wm   = (wid >> 1) * 32;
    int wn   = (wid & 1) * 64;
    int m0   = blockIdx.y << 7;
    int n0   = blockIdx.x << 7;

    float acc[2][8][4];
    #pragma unroll
    for (int mi = 0; mi < 2; mi++)
        #pragma unroll
        for (int ni = 0; ni < 8; ni++)
            #pragma unroll
            for (int r = 0; r < 4; r++) acc[mi][ni][r] = 0.f;

    const int nk = K >> 4;

    // prologue: chunk 0 -> buffer 0
    stage_rm(Ah, K, m0, 0, SAh, tid);
    stage_rm(Al, K, m0, 0, SAl, tid);
    if (!TRANSB) { stage_cm(Bh, N, n0, 0, SBh, tid); stage_cm(Bl, N, n0, 0, SBl, tid); }
    else         { stage_rm(Bh, K, n0, 0, SBh, tid); stage_rm(Bl, K, n0, 0, SBl, tid); }
    __syncthreads();

    for (int kc = 0; kc < nk; kc++) {
        int buf = kc & 1;
        if (kc + 1 < nk) {
            int k0 = (kc + 1) << 4;
            int nb = buf ^ 1;
            stage_rm(Ah, K, m0, k0, SAh + nb*BUFU, tid);
            stage_rm(Al, K, m0, k0, SAl + nb*BUFU, tid);
            if (!TRANSB) { stage_cm(Bh, N, n0, k0, SBh + nb*BUFU, tid); stage_cm(Bl, N, n0, k0, SBl + nb*BUFU, tid); }
            else         { stage_rm(Bh, K, n0, k0, SBh + nb*BUFU, tid); stage_rm(Bl, K, n0, k0, SBl + nb*BUFU, tid); }
        }

        const float* Abh = SAh + buf*BUFU;
        const float* Abl = SAl + buf*BUFU;
        const float* Bbh = SBh + buf*BUFU;
        const float* Bbl = SBl + buf*BUFU;
        #pragma unroll
        for (int ks = 0; ks < 2; ks++) {
            int kb = ks << 3;
            unsigned ah[2][4], al[2][4];
            #pragma unroll
            for (int mi = 0; mi < 2; mi++) {
                int mb = wm + mi*16;
                ah[mi][0] = __float_as_uint(Abh[(kb+tg  )*PADW + mb+gr  ]);
                ah[mi][1] = __float_as_uint(Abh[(kb+tg  )*PADW + mb+gr+8]);
                ah[mi][2] = __float_as_uint(Abh[(kb+tg+4)*PADW + mb+gr  ]);
                ah[mi][3] = __float_as_uint(Abh[(kb+tg+4)*PADW + mb+gr+8]);
                al[mi][0] = __float_as_uint(Abl[(kb+tg  )*PADW + mb+gr  ]);
                al[mi][1] = __float_as_uint(Abl[(kb+tg  )*PADW + mb+gr+8]);
                al[mi][2] = __float_as_uint(Abl[(kb+tg+4)*PADW + mb+gr  ]);
                al[mi][3] = __float_as_uint(Abl[(kb+tg+4)*PADW + mb+gr+8]);
            }
            #pragma unroll
            for (int ni = 0; ni < 8; ni++) {
                int nb2 = wn + ni*8 + gr;
                unsigned bh[2], bl[2];
                bh[0] = __float_as_uint(Bbh[(kb+tg  )*PADW + nb2]);
                bh[1] = __float_as_uint(Bbh[(kb+tg+4)*PADW + nb2]);
                bl[0] = __float_as_uint(Bbl[(kb+tg  )*PADW + nb2]);
                bl[1] = __float_as_uint(Bbl[(kb+tg+4)*PADW + nb2]);
                #pragma unroll
                for (int mi = 0; mi < 2; mi++) {
                    mma_tf32(acc[mi][ni], al[mi], bh);
                    mma_tf32(acc[mi][ni], ah[mi], bl);
                    mma_tf32(acc[mi][ni], ah[mi], bh);
                }
            }
        }
        __syncthreads();
    }

    // epilogue
    #pragma unroll
    for (int mi = 0; mi < 2; mi++) {
        int r0 = m0 + wm + mi*16 + gr;
        #pragma unroll
        for (int ni = 0; ni < 8; ni++) {
            int c0 = n0 + wn + ni*8 + tg*2;
            float* p0 = &C[(size_t)r0*N + c0];
            float* p1 = &C[(size_t)(r0+8)*N + c0];
            if (ACC) {
                p0[0] += acc[mi][ni][0]; p0[1] += acc[mi][ni][1];
                p1[0] += acc[mi][ni][2]; p1[1] += acc[mi][ni][3];
            } else {
                p0[0] = acc[mi][ni][0]; p0[1] = acc[mi][ni][1];
                p1[0] = acc[mi][ni][2]; p1[1] = acc[mi][ni][3];
            }
        }
    }
}

// ---------------- fused flash attention ----------------
#define ATTN_SMEM_BYTES ((3*64*65 + 64*64) * 4)

__global__ void __launch_bounds__(256)
attn_fused_kernel() {
    extern __shared__ float sm[];
    float (*Qs)[65] = (float(*)[65])sm;
    float (*Ks)[65] = (float(*)[65])(sm + 64*65);
    float (*Ps)[65] = (float(*)[65])(sm + 2*64*65);
    float (*Vs)[64] = (float(*)[64])(sm + 3*64*65);

    int bh = blockIdx.z;
    int b = bh >> 4, h = bh & 15;
    int it = blockIdx.y;
    int i0 = it << 6;
    int tid = threadIdx.x;
    int tx = tid & 15, ty = tid >> 4;

    #pragma unroll
    for (int e = 0; e < 16; e++) {
        int lin = tid + e*256;
        int r = lin >> 6, c = lin & 63;
        Qs[r][c] = g_q[(size_t)(b*SS + i0 + r)*DD + h*HD + c];
    }

    float m_run[4], l_run[4], o[4][4];
    #pragma unroll
    for (int i = 0; i < 4; i++) {
        m_run[i] = -1e30f; l_run[i] = 0.f;
        #pragma unroll
        for (int j = 0; j < 4; j++) o[i][j] = 0.f;
    }

    for (int jt = 0; jt <= it; jt++) {
        int j0 = jt << 6;
        #pragma unroll
        for (int e = 0; e < 16; e++) {
            int lin = tid + e*256;
            int r = lin >> 6, c = lin & 63;
            Ks[r][c] = g_k[(size_t)(b*SS + j0 + r)*DD + h*HD + c];
            Vs[r][c] = g_v[(size_t)(b*SS + j0 + r)*DD + h*HD + c];
        }
        __syncthreads();

        float s[4][4] = {};
        #pragma unroll 8
        for (int kk = 0; kk < 64; kk++) {
            float a[4], bb[4];
            #pragma unroll
            for (int i = 0; i < 4; i++) a[i]  = Qs[ty*4+i][kk];
            #pragma unroll
            for (int j = 0; j < 4; j++) bb[j] = Ks[tx*4+j][kk];
            #pragma unroll
            for (int i = 0; i < 4; i++)
                #pragma unroll
                for (int j = 0; j < 4; j++)
                    s[i][j] += a[i]*bb[j];
        }

        #pragma unroll
        for (int i = 0; i < 4; i++) {
            int gi = i0 + ty*4 + i;
            #pragma unroll
            for (int j = 0; j < 4; j++) {
                int gj = j0 + tx*4 + j;
                s[i][j] = (gj > gi) ? -1e30f : s[i][j]*0.125f;
            }
        }

        #pragma unroll
        for (int i = 0; i < 4; i++) {
            float mloc = fmaxf(fmaxf(s[i][0], s[i][1]), fmaxf(s[i][2], s[i][3]));
            #pragma unroll
            for (int off = 8; off > 0; off >>= 1)
                mloc = fmaxf(mloc, __shfl_xor_sync(0xffffffffu, mloc, off));
            float m_new = fmaxf(m_run[i], mloc);
            float corr = __expf(m_run[i] - m_new);
            l_run[i] *= corr;
            #pragma unroll
            for (int j = 0; j < 4; j++) o[i][j] *= corr;
            float rs = 0.f;
            #pragma unroll
            for (int j = 0; j < 4; j++) {
                s[i][j] = __expf(s[i][j] - m_new);
                rs += s[i][j];
            }
            #pragma unroll
            for (int off = 8; off > 0; off >>= 1)
                rs += __shfl_xor_sync(0xffffffffu, rs, off);
            l_run[i] += rs;
            m_run[i] = m_new;
        }

        #pragma unroll
        for (int i = 0; i < 4; i++)
            #pragma unroll
            for (int j = 0; j < 4; j++)
                Ps[ty*4+i][tx*4+j] = s[i][j];
        __syncthreads();

        #pragma unroll 8
        for (int kk = 0; kk < 64; kk++) {
            float a[4];
            #pragma unroll
            for (int i = 0; i < 4; i++) a[i] = Ps[ty*4+i][kk];
            float4 v4 = *(const float4*)&Vs[kk][tx*4];
            float bv[4] = {v4.x, v4.y, v4.z, v4.w};
            #pragma unroll
            for (int i = 0; i < 4; i++)
                #pragma unroll
                for (int j = 0; j < 4; j++)
                    o[i][j] += a[i]*bv[j];
        }
        __syncthreads();
    }

    #pragma unroll
    for (int i = 0; i < 4; i++) {
        float inv = 1.0f / l_run[i];
        #pragma unroll
        for (int j = 0; j < 4; j++) {
            size_t idx = (size_t)(b*SS + i0 + ty*4 + i)*DD + h*HD + tx*4 + j;
            float2 s2 = split_tf2(o[i][j]*inv);
            g_ao_hi[idx] = s2.x;
            g_ao_lo[idx] = s2.y;
        }
    }
}

// ---------------- host launcher ----------------
static inline void split_all(const float* src, float* hi, float* lo, size_t n) {
    int n4 = (int)(n >> 2);
    split4_kernel<<<(n4 + 255)/256, 256>>>((const float4*)src, (float4*)hi, (float4*)lo, n4);
}

extern "C" void kernel_launch(void* const* d_in, const int* in_sizes, int n_in,
                              void* d_out, int out_size) {
    const int*   tokens     = (const int*)  d_in[0];
    const float* emb        = (const float*)d_in[1];
    const float* wq         = (const float*)d_in[2];
    const float* wk         = (const float*)d_in[3];
    const float* wv         = (const float*)d_in[4];
    const float* wo         = (const float*)d_in[5];
    const float* w1         = (const float*)d_in[6];
    const float* w2         = (const float*)d_in[7];
    const float* w3         = (const float*)d_in[8];
    const float* attn_norm  = (const float*)d_in[9];
    const float* ffn_norm   = (const float*)d_in[10];
    const float* final_norm = (const float*)d_in[11];
    float* out = (float*)d_out;
    (void)in_sizes; (void)n_in; (void)out_size;

    float *p_h, *p_q, *p_k, *p_v, *p_f1, *p_f3;
    cudaGetSymbolAddress((void**)&p_h,  g_h);
    cudaGetSymbolAddress((void**)&p_q,  g_q);
    cudaGetSymbolAddress((void**)&p_k,  g_k);
    cudaGetSymbolAddress((void**)&p_v,  g_v);
    cudaGetSymbolAddress((void**)&p_f1, g_f1);
    cudaGetSymbolAddress((void**)&p_f3, g_f3);

    float *hn_hi, *hn_lo, *ao_hi, *ao_lo, *f1_hi, *f1_lo;
    cudaGetSymbolAddress((void**)&hn_hi, g_hn_hi);
    cudaGetSymbolAddress((void**)&hn_lo, g_hn_lo);
    cudaGetSymbolAddress((void**)&ao_hi, g_ao_hi);
    cudaGetSymbolAddress((void**)&ao_lo, g_ao_lo);
    cudaGetSymbolAddress((void**)&f1_hi, g_f1_hi);
    cudaGetSymbolAddress((void**)&f1_lo, g_f1_lo);

    float *wq_hi,*wq_lo,*wk_hi,*wk_lo,*wv_hi,*wv_lo,*wo_hi,*wo_lo;
    float *w1_hi,*w1_lo,*w3_hi,*w3_lo,*w2_hi,*w2_lo,*emb_hi,*emb_lo;
    cudaGetSymbolAddress((void**)&wq_hi, g_wq_hi); cudaGetSymbolAddress((void**)&wq_lo, g_wq_lo);
    cudaGetSymbolAddress((void**)&wk_hi, g_wk_hi); cudaGetSymbolAddress((void**)&wk_lo, g_wk_lo);
    cudaGetSymbolAddress((void**)&wv_hi, g_wv_hi); cudaGetSymbolAddress((void**)&wv_lo, g_wv_lo);
    cudaGetSymbolAddress((void**)&wo_hi, g_wo_hi); cudaGetSymbolAddress((void**)&wo_lo, g_wo_lo);
    cudaGetSymbolAddress((void**)&w1_hi, g_w1_hi); cudaGetSymbolAddress((void**)&w1_lo, g_w1_lo);
    cudaGetSymbolAddress((void**)&w3_hi, g_w3_hi); cudaGetSymbolAddress((void**)&w3_lo, g_w3_lo);
    cudaGetSymbolAddress((void**)&w2_hi, g_w2_hi); cudaGetSymbolAddress((void**)&w2_lo, g_w2_lo);
    cudaGetSymbolAddress((void**)&emb_hi, g_emb_hi); cudaGetSymbolAddress((void**)&emb_lo, g_emb_lo);

    cudaFuncSetAttribute(gemm4_kernel<0,0>, cudaFuncAttributeMaxDynamicSharedMemorySize, GEMM_SMEM_BYTES);
    cudaFuncSetAttribute(gemm4_kernel<0,1>, cudaFuncAttributeMaxDynamicSharedMemorySize, GEMM_SMEM_BYTES);
    cudaFuncSetAttribute(gemm4_kernel<1,0>, cudaFuncAttributeMaxDynamicSharedMemorySize, GEMM_SMEM_BYTES);
    cudaFuncSetAttribute(attn_fused_kernel, cudaFuncAttributeMaxDynamicSharedMemorySize, ATTN_SMEM_BYTES);

    // pre-split weights + embedding (DRAM nearly idle; ~120us total)
    split_all(wq,  wq_hi,  wq_lo,  (size_t)LL*DD*DD);
    split_all(wk,  wk_hi,  wk_lo,  (size_t)LL*DD*DD);
    split_all(wv,  wv_hi,  wv_lo,  (size_t)LL*DD*DD);
    split_all(wo,  wo_hi,  wo_lo,  (size_t)LL*DD*DD);
    split_all(w1,  w1_hi,  w1_lo,  (size_t)LL*DD*FFD);
    split_all(w3,  w3_hi,  w3_lo,  (size_t)LL*DD*FFD);
    split_all(w2,  w2_hi,  w2_lo,  (size_t)LL*FFD*DD);
    split_all(emb, emb_hi, emb_lo, (size_t)VV*DD);

    rope_tables_kernel<<<(SS*(HD/2)+255)/256, 256>>>();
    embed_kernel<<<(MROWS*DD+255)/256, 256>>>(tokens, emb);

    for (int l = 0; l < LL; l++) {
        // attention block
        rmsnorm_split_kernel<<<MROWS, 256>>>(p_h, attn_norm + l*DD, hn_hi, hn_lo);
        gemm4_kernel<0,0><<<dim3(DD/128, MROWS/128), 256, GEMM_SMEM_BYTES>>>(hn_hi, hn_lo, wq_hi + (size_t)l*DD*DD, wq_lo + (size_t)l*DD*DD, p_q, MROWS, DD, DD);
        gemm4_kernel<0,0><<<dim3(DD/128, MROWS/128), 256, GEMM_SMEM_BYTES>>>(hn_hi, hn_lo, wk_hi + (size_t)l*DD*DD, wk_lo + (size_t)l*DD*DD, p_k, MROWS, DD, DD);
        gemm4_kernel<0,0><<<dim3(DD/128, MROWS/128), 256, GEMM_SMEM_BYTES>>>(hn_hi, hn_lo, wv_hi + (size_t)l*DD*DD, wv_lo + (size_t)l*DD*DD, p_v, MROWS, DD, DD);
        rope_kernel<<<(BB*SS*HH*(HD/2)+255)/256, 256>>>(p_q);
        rope_kernel<<<(BB*SS*HH*(HD/2)+255)/256, 256>>>(p_k);
        attn_fused_kernel<<<dim3(1, SS/64, BB*HH), 256, ATTN_SMEM_BYTES>>>();
        gemm4_kernel<0,1><<<dim3(DD/128, MROWS/128), 256, GEMM_SMEM_BYTES>>>(ao_hi, ao_lo, wo_hi + (size_t)l*DD*DD, wo_lo + (size_t)l*DD*DD, p_h, MROWS, DD, DD);

        // FFN block
        rmsnorm_split_kernel<<<MROWS, 256>>>(p_h, ffn_norm + l*DD, hn_hi, hn_lo);
        gemm4_kernel<0,0><<<dim3(FFD/128, MROWS/128), 256, GEMM_SMEM_BYTES>>>(hn_hi, hn_lo, w1_hi + (size_t)l*DD*FFD, w1_lo + (size_t)l*DD*FFD, p_f1, MROWS, FFD, DD);
        gemm4_kernel<0,0><<<dim3(FFD/128, MROWS/128), 256, GEMM_SMEM_BYTES>>>(hn_hi, hn_lo, w3_hi + (size_t)l*DD*FFD, w3_lo + (size_t)l*DD*FFD, p_f3, MROWS, FFD, DD);
        silu_mul_kernel<<<(MROWS*FFD+255)/256, 256>>>();
        gemm4_kernel<0,1><<<dim3(DD/128, MROWS/128), 256, GEMM_SMEM_BYTES>>>(f1_hi, f1_lo, w2_hi + (size_t)l*FFD*DD, w2_lo + (size_t)l*FFD*DD, p_h, MROWS, DD, FFD);
    }

    rmsnorm_split_kernel<<<MROWS, 256>>>(p_h, final_norm, hn_hi, hn_lo);
    gemm4_kernel<1,0><<<dim3(VV/128, MROWS/128), 256, GEMM_SMEM_BYTES>>>(hn_hi, hn_lo, emb_hi, emb_lo, out, MROWS, VV, DD);
}

// round 12
// speedup vs baseline: 1.4202x; 1.4202x over previous
#include <cuda_runtime.h>
#include <math.h>

#define BB 2
#define SS 1024
#define DD 1024
#define HH 16
#define HD 64
#define LL 4
#define FFD 2816
#define VV 32000
#define MROWS (BB*SS)   // 2048
#define EPSV 1e-6f

// ---------------- scratch (device globals; no allocations) ----------------
__device__ float g_h  [MROWS*DD];
__device__ float g_hn [MROWS*DD];
__device__ float g_q  [MROWS*DD];
__device__ float g_k  [MROWS*DD];
__device__ float g_v  [MROWS*DD];
__device__ float g_ao [MROWS*DD];
__device__ float g_f1 [MROWS*FFD];
__device__ float g_f3 [MROWS*FFD];
__device__ float g_cos[SS*(HD/2)];
__device__ float g_sin[SS*(HD/2)];

// ---------------- small elementwise kernels ----------------
__global__ void rope_tables_kernel() {
    int idx = blockIdx.x*blockDim.x + threadIdx.x;
    if (idx >= SS*(HD/2)) return;
    int s = idx / (HD/2);
    int j = idx % (HD/2);
    float inv = powf(10000.0f, -2.0f*(float)j/(float)HD);
    float ang = (float)s * inv;
    g_cos[idx] = cosf(ang);
    g_sin[idx] = sinf(ang);
}

__global__ void embed_kernel(const int* __restrict__ tokens, const float* __restrict__ emb) {
    int idx = blockIdx.x*blockDim.x + threadIdx.x;
    if (idx >= MROWS*DD) return;
    int row = idx / DD;
    int d   = idx % DD;
    g_h[idx] = emb[(size_t)tokens[row]*DD + d];
}

__global__ void rope_kernel(float* __restrict__ x) {
    int idx = blockIdx.x*blockDim.x + threadIdx.x;
    const int total = BB*SS*HH*(HD/2);
    if (idx >= total) return;
    int j = idx % (HD/2);
    int h = (idx/(HD/2)) % HH;
    int s = (idx/(HD/2)/HH) % SS;
    int b =  idx/(HD/2)/HH/SS;
    float c  = g_cos[s*(HD/2)+j];
    float sn = g_sin[s*(HD/2)+j];
    size_t base = (size_t)(b*SS+s)*DD + h*HD + 2*j;
    float x0 = x[base], x1 = x[base+1];
    x[base]   = x0*c - x1*sn;
    x[base+1] = x0*sn + x1*c;
}

__global__ void rmsnorm_kernel(const float* __restrict__ x, const float* __restrict__ w,
                               float* __restrict__ out) {
    int row = blockIdx.x;
    int t   = threadIdx.x;
    const float* xr = x + (size_t)row*DD;
    float v[4];
    float ss = 0.f;
    #pragma unroll
    for (int e = 0; e < 4; e++) { v[e] = xr[t + e*256]; ss += v[e]*v[e]; }
    __shared__ float red[256];
    red[t] = ss; __syncthreads();
    for (int off = 128; off > 0; off >>= 1) {
        if (t < off) red[t] += red[t+off];
        __syncthreads();
    }
    float scale = rsqrtf(red[0]/(float)DD + EPSV);
    #pragma unroll
    for (int e = 0; e < 4; e++) {
        int d = t + e*256;
        out[(size_t)row*DD + d] = v[e]*scale*w[d];
    }
}

__global__ void silu_mul_kernel() {
    int idx = blockIdx.x*blockDim.x + threadIdx.x;
    if (idx >= MROWS*FFD) return;
    float a = g_f1[idx];
    float sig = 1.0f / (1.0f + __expf(-a));
    g_f1[idx] = a*sig*g_f3[idx];
}

// ---------------- TF32 helpers ----------------
__device__ __forceinline__ unsigned f2tf(float f) {
    unsigned u;
    asm("cvt.rna.tf32.f32 %0, %1;" : "=r"(u) : "f"(f));
    return u;
}
__device__ __forceinline__ void split_tf(float f, unsigned& hi, unsigned& lo) {
    hi = f2tf(f);
    lo = f2tf(f - __uint_as_float(hi));
}
__device__ __forceinline__ void mma_tf32(float* c, const unsigned* a, const unsigned* b) {
    asm volatile(
        "mma.sync.aligned.m16n8k8.row.col.f32.tf32.tf32.f32 "
        "{%0,%1,%2,%3}, {%4,%5,%6,%7}, {%8,%9}, {%0,%1,%2,%3};\n"
        : "+f"(c[0]), "+f"(c[1]), "+f"(c[2]), "+f"(c[3])
        : "r"(a[0]), "r"(a[1]), "r"(a[2]), "r"(a[3]), "r"(b[0]), "r"(b[1]));
}

#define PADW 136

// ---------------- 3xTF32 GEMM (fp32-accurate), register-side split ----------------
// C[M,N] = A[M,K] @ B[K,N] (TRANSB=0) or A[M,K] @ B[N,K]^T (TRANSB=1)
// Block tile 128x128, K-chunk 16, 8 warps 4(m)x2(n), warp tile 32x64, m16n8k8.
template<int TRANSB, int ACC>
__global__ void __launch_bounds__(256, 2)
gemm_tf32x3_kernel(const float* __restrict__ A, const float* __restrict__ B,
                   float* __restrict__ C, int M, int N, int K) {
    __shared__ float As[2][16][PADW];   // [k][m], raw fp32
    __shared__ float Bs[2][16][PADW];   // [k][n], raw fp32

    int tid  = threadIdx.x;
    int lane = tid & 31;
    int gr   = lane >> 2;     // 0..7
    int tg   = lane & 3;      // 0..3
    int wid  = tid >> 5;      // 0..7
    int wm   = (wid >> 1) * 32;
    int wn   = (wid & 1) * 64;
    int m0   = blockIdx.y << 7;
    int n0   = blockIdx.x << 7;

    float acc[2][8][4];
    #pragma unroll
    for (int mi = 0; mi < 2; mi++)
        #pragma unroll
        for (int ni = 0; ni < 8; ni++)
            #pragma unroll
            for (int r = 0; r < 4; r++) acc[mi][ni][r] = 0.f;

    const int nk = K >> 4;

    // ---- prologue: load chunk 0 into buffer 0 ----
    {
        #pragma unroll
        for (int e = 0; e < 2; e++) {
            int idx = tid + e*256;
            int row = idx >> 2;              // 0..127 (m)
            int kq  = (idx & 3) << 2;        // 0,4,8,12
            float4 a4 = *(const float4*)&A[(size_t)(m0+row)*K + kq];
            As[0][kq+0][row] = a4.x;
            As[0][kq+1][row] = a4.y;
            As[0][kq+2][row] = a4.z;
            As[0][kq+3][row] = a4.w;
        }
        if (!TRANSB) {
            #pragma unroll
            for (int e = 0; e < 2; e++) {
                int idx = tid + e*256;
                int k  = idx >> 5;           // 0..15
                int nq = (idx & 31) << 2;    // 0..124
                float4 b4 = *(const float4*)&B[(size_t)k*N + n0 + nq];
                *(float4*)&Bs[0][k][nq] = b4;
            }
        } else {
            #pragma unroll
            for (int e = 0; e < 2; e++) {
                int idx = tid + e*256;
                int row = idx >> 2;          // n, 0..127
                int kq  = (idx & 3) << 2;
                float4 b4 = *(const float4*)&B[(size_t)(n0+row)*K + kq];
                Bs[0][kq+0][row] = b4.x;
                Bs[0][kq+1][row] = b4.y;
                Bs[0][kq+2][row] = b4.z;
                Bs[0][kq+3][row] = b4.w;
            }
        }
    }
    __syncthreads();

    for (int kc = 0; kc < nk; kc++) {
        int buf = kc & 1;
        // ---- prefetch next chunk into other buffer ----
        if (kc + 1 < nk) {
            int k0 = (kc + 1) << 4;
            int nb = buf ^ 1;
            #pragma unroll
            for (int e = 0; e < 2; e++) {
                int idx = tid + e*256;
                int row = idx >> 2;
                int kq  = (idx & 3) << 2;
                float4 a4 = *(const float4*)&A[(size_t)(m0+row)*K + k0 + kq];
                As[nb][kq+0][row] = a4.x;
                As[nb][kq+1][row] = a4.y;
                As[nb][kq+2][row] = a4.z;
                As[nb][kq+3][row] = a4.w;
            }
            if (!TRANSB) {
                #pragma unroll
                for (int e = 0; e < 2; e++) {
                    int idx = tid + e*256;
                    int k  = idx >> 5;
                    int nq = (idx & 31) << 2;
                    float4 b4 = *(const float4*)&B[(size_t)(k0+k)*N + n0 + nq];
                    *(float4*)&Bs[nb][k][nq] = b4;
                }
            } else {
                #pragma unroll
                for (int e = 0; e < 2; e++) {
                    int idx = tid + e*256;
                    int row = idx >> 2;
                    int kq  = (idx & 3) << 2;
                    float4 b4 = *(const float4*)&B[(size_t)(n0+row)*K + k0 + kq];
                    Bs[nb][kq+0][row] = b4.x;
                    Bs[nb][kq+1][row] = b4.y;
                    Bs[nb][kq+2][row] = b4.z;
                    Bs[nb][kq+3][row] = b4.w;
                }
            }
        }

        // ---- compute on current buffer ----
        #pragma unroll
        for (int ks = 0; ks < 2; ks++) {
            int kb = ks << 3;
            unsigned ah[2][4], al[2][4];
            #pragma unroll
            for (int mi = 0; mi < 2; mi++) {
                int mb = wm + mi*16;
                split_tf(As[buf][kb+tg  ][mb+gr  ], ah[mi][0], al[mi][0]);
                split_tf(As[buf][kb+tg  ][mb+gr+8], ah[mi][1], al[mi][1]);
                split_tf(As[buf][kb+tg+4][mb+gr  ], ah[mi][2], al[mi][2]);
                split_tf(As[buf][kb+tg+4][mb+gr+8], ah[mi][3], al[mi][3]);
            }
            #pragma unroll
            for (int ni = 0; ni < 8; ni++) {
                int nb2 = wn + ni*8 + gr;
                unsigned bh[2], bl[2];
                split_tf(Bs[buf][kb+tg  ][nb2], bh[0], bl[0]);
                split_tf(Bs[buf][kb+tg+4][nb2], bh[1], bl[1]);
                #pragma unroll
                for (int mi = 0; mi < 2; mi++) {
                    mma_tf32(acc[mi][ni], al[mi], bh);
                    mma_tf32(acc[mi][ni], ah[mi], bl);
                    mma_tf32(acc[mi][ni], ah[mi], bh);
                }
            }
        }
        __syncthreads();
    }

    // ---- epilogue ----
    #pragma unroll
    for (int mi = 0; mi < 2; mi++) {
        int r0 = m0 + wm + mi*16 + gr;
        #pragma unroll
        for (int ni = 0; ni < 8; ni++) {
            int c0 = n0 + wn + ni*8 + tg*2;
            float* p0 = &C[(size_t)r0*N + c0];
            float* p1 = &C[(size_t)(r0+8)*N + c0];
            if (ACC) {
                p0[0] += acc[mi][ni][0]; p0[1] += acc[mi][ni][1];
                p1[0] += acc[mi][ni][2]; p1[1] += acc[mi][ni][3];
            } else {
                p0[0] = acc[mi][ni][0]; p0[1] = acc[mi][ni][1];
                p1[0] = acc[mi][ni][2]; p1[1] = acc[mi][ni][3];
            }
        }
    }
}

// ---------------- pure TF32 GEMM (1 MMA), for the final logits only ----------------
// C[M,N] = A[M,K] @ B[N,K]^T. smem holds tf32-converted values; inner loop pure LDS+MMA.
__global__ void __launch_bounds__(256, 2)
gemm_tf32x1_nt_kernel(const float* __restrict__ A, const float* __restrict__ B,
                      float* __restrict__ C, int M, int N, int K) {
    __shared__ unsigned As[2][16][PADW];   // [k][m], tf32
    __shared__ unsigned Bs[2][16][PADW];   // [k][n], tf32

    int tid  = threadIdx.x;
    int lane = tid & 31;
    int gr   = lane >> 2;
    int tg   = lane & 3;
    int wid  = tid >> 5;
    int wm   = (wid >> 1) * 32;
    int wn   = (wid & 1) * 64;
    int m0   = blockIdx.y << 7;
    int n0   = blockIdx.x << 7;

    float acc[2][8][4];
    #pragma unroll
    for (int mi = 0; mi < 2; mi++)
        #pragma unroll
        for (int ni = 0; ni < 8; ni++)
            #pragma unroll
            for (int r = 0; r < 4; r++) acc[mi][ni][r] = 0.f;

    const int nk = K >> 4;

    // prologue
    {
        #pragma unroll
        for (int e = 0; e < 2; e++) {
            int idx = tid + e*256;
            int row = idx >> 2;
            int kq  = (idx & 3) << 2;
            float4 a4 = *(const float4*)&A[(size_t)(m0+row)*K + kq];
            As[0][kq+0][row] = f2tf(a4.x);
            As[0][kq+1][row] = f2tf(a4.y);
            As[0][kq+2][row] = f2tf(a4.z);
            As[0][kq+3][row] = f2tf(a4.w);
            float4 b4 = *(const float4*)&B[(size_t)(n0+row)*K + kq];
            Bs[0][kq+0][row] = f2tf(b4.x);
            Bs[0][kq+1][row] = f2tf(b4.y);
            Bs[0][kq+2][row] = f2tf(b4.z);
            Bs[0][kq+3][row] = f2tf(b4.w);
        }
    }
    __syncthreads();

    for (int kc = 0; kc < nk; kc++) {
        int buf = kc & 1;
        if (kc + 1 < nk) {
            int k0 = (kc + 1) << 4;
            int nb = buf ^ 1;
            #pragma unroll
            for (int e = 0; e < 2; e++) {
                int idx = tid + e*256;
                int row = idx >> 2;
                int kq  = (idx & 3) << 2;
                float4 a4 = *(const float4*)&A[(size_t)(m0+row)*K + k0 + kq];
                As[nb][kq+0][row] = f2tf(a4.x);
                As[nb][kq+1][row] = f2tf(a4.y);
                As[nb][kq+2][row] = f2tf(a4.z);
                As[nb][kq+3][row] = f2tf(a4.w);
                float4 b4 = *(const float4*)&B[(size_t)(n0+row)*K + k0 + kq];
                Bs[nb][kq+0][row] = f2tf(b4.x);
                Bs[nb][kq+1][row] = f2tf(b4.y);
                Bs[nb][kq+2][row] = f2tf(b4.z);
                Bs[nb][kq+3][row] = f2tf(b4.w);
            }
        }

        #pragma unroll
        for (int ks = 0; ks < 2; ks++) {
            int kb = ks << 3;
            unsigned a[2][4];
            #pragma unroll
            for (int mi = 0; mi < 2; mi++) {
                int mb = wm + mi*16;
                a[mi][0] = As[buf][kb+tg  ][mb+gr  ];
                a[mi][1] = As[buf][kb+tg  ][mb+gr+8];
                a[mi][2] = As[buf][kb+tg+4][mb+gr  ];
                a[mi][3] = As[buf][kb+tg+4][mb+gr+8];
            }
            #pragma unroll
            for (int ni = 0; ni < 8; ni++) {
                int nb2 = wn + ni*8 + gr;
                unsigned b[2];
                b[0] = Bs[buf][kb+tg  ][nb2];
                b[1] = Bs[buf][kb+tg+4][nb2];
                #pragma unroll
                for (int mi = 0; mi < 2; mi++)
                    mma_tf32(acc[mi][ni], a[mi], b);
            }
        }
        __syncthreads();
    }

    #pragma unroll
    for (int mi = 0; mi < 2; mi++) {
        int r0 = m0 + wm + mi*16 + gr;
        #pragma unroll
        for (int ni = 0; ni < 8; ni++) {
            int c0 = n0 + wn + ni*8 + tg*2;
            C[(size_t)r0*N + c0 + 0] = acc[mi][ni][0];
            C[(size_t)r0*N + c0 + 1] = acc[mi][ni][1];
            C[(size_t)(r0+8)*N + c0 + 0] = acc[mi][ni][2];
            C[(size_t)(r0+8)*N + c0 + 1] = acc[mi][ni][3];
        }
    }
}

// ---------------- fused flash attention ----------------
#define ATTN_SMEM_BYTES ((3*64*65 + 64*64) * 4)

__global__ void __launch_bounds__(256)
attn_fused_kernel() {
    extern __shared__ float sm[];
    float (*Qs)[65] = (float(*)[65])sm;
    float (*Ks)[65] = (float(*)[65])(sm + 64*65);
    float (*Ps)[65] = (float(*)[65])(sm + 2*64*65);
    float (*Vs)[64] = (float(*)[64])(sm + 3*64*65);

    int bh = blockIdx.z;
    int b = bh >> 4, h = bh & 15;
    int it = blockIdx.y;
    int i0 = it << 6;
    int tid = threadIdx.x;
    int tx = tid & 15, ty = tid >> 4;

    #pragma unroll
    for (int e = 0; e < 16; e++) {
        int lin = tid + e*256;
        int r = lin >> 6, c = lin & 63;
        Qs[r][c] = g_q[(size_t)(b*SS + i0 + r)*DD + h*HD + c];
    }

    float m_run[4], l_run[4], o[4][4];
    #pragma unroll
    for (int i = 0; i < 4; i++) {
        m_run[i] = -1e30f; l_run[i] = 0.f;
        #pragma unroll
        for (int j = 0; j < 4; j++) o[i][j] = 0.f;
    }

    for (int jt = 0; jt <= it; jt++) {
        int j0 = jt << 6;
        #pragma unroll
        for (int e = 0; e < 16; e++) {
            int lin = tid + e*256;
            int r = lin >> 6, c = lin & 63;
            Ks[r][c] = g_k[(size_t)(b*SS + j0 + r)*DD + h*HD + c];
            Vs[r][c] = g_v[(size_t)(b*SS + j0 + r)*DD + h*HD + c];
        }
        __syncthreads();

        float s[4][4] = {};
        #pragma unroll 8
        for (int kk = 0; kk < 64; kk++) {
            float a[4], bb[4];
            #pragma unroll
            for (int i = 0; i < 4; i++) a[i]  = Qs[ty*4+i][kk];
            #pragma unroll
            for (int j = 0; j < 4; j++) bb[j] = Ks[tx*4+j][kk];
            #pragma unroll
            for (int i = 0; i < 4; i++)
                #pragma unroll
                for (int j = 0; j < 4; j++)
                    s[i][j] += a[i]*bb[j];
        }

        #pragma unroll
        for (int i = 0; i < 4; i++) {
            int gi = i0 + ty*4 + i;
            #pragma unroll
            for (int j = 0; j < 4; j++) {
                int gj = j0 + tx*4 + j;
                s[i][j] = (gj > gi) ? -1e30f : s[i][j]*0.125f;
            }
        }

        #pragma unroll
        for (int i = 0; i < 4; i++) {
            float mloc = fmaxf(fmaxf(s[i][0], s[i][1]), fmaxf(s[i][2], s[i][3]));
            #pragma unroll
            for (int off = 8; off > 0; off >>= 1)
                mloc = fmaxf(mloc, __shfl_xor_sync(0xffffffffu, mloc, off));
            float m_new = fmaxf(m_run[i], mloc);
            float corr = __expf(m_run[i] - m_new);
            l_run[i] *= corr;
            #pragma unroll
            for (int j = 0; j < 4; j++) o[i][j] *= corr;
            float rs = 0.f;
            #pragma unroll
            for (int j = 0; j < 4; j++) {
                s[i][j] = __expf(s[i][j] - m_new);
                rs += s[i][j];
            }
            #pragma unroll
            for (int off = 8; off > 0; off >>= 1)
                rs += __shfl_xor_sync(0xffffffffu, rs, off);
            l_run[i] += rs;
            m_run[i] = m_new;
        }

        #pragma unroll
        for (int i = 0; i < 4; i++)
            #pragma unroll
            for (int j = 0; j < 4; j++)
                Ps[ty*4+i][tx*4+j] = s[i][j];
        __syncthreads();

        #pragma unroll 8
        for (int kk = 0; kk < 64; kk++) {
            float a[4];
            #pragma unroll
            for (int i = 0; i < 4; i++) a[i] = Ps[ty*4+i][kk];
            float4 v4 = *(const float4*)&Vs[kk][tx*4];
            float bv[4] = {v4.x, v4.y, v4.z, v4.w};
            #pragma unroll
            for (int i = 0; i < 4; i++)
                #pragma unroll
                for (int j = 0; j < 4; j++)
                    o[i][j] += a[i]*bv[j];
        }
        __syncthreads();
    }

    #pragma unroll
    for (int i = 0; i < 4; i++) {
        float inv = 1.0f / l_run[i];
        #pragma unroll
        for (int j = 0; j < 4; j++)
            g_ao[(size_t)(b*SS + i0 + ty*4 + i)*DD + h*HD + tx*4 + j] = o[i][j]*inv;
    }
}

// ---------------- host launcher ----------------
extern "C" void kernel_launch(void* const* d_in, const int* in_sizes, int n_in,
                              void* d_out, int out_size) {
    const int*   tokens     = (const int*)  d_in[0];
    const float* emb        = (const float*)d_in[1];
    const float* wq         = (const float*)d_in[2];
    const float* wk         = (const float*)d_in[3];
    const float* wv         = (const float*)d_in[4];
    const float* wo         = (const float*)d_in[5];
    const float* w1         = (const float*)d_in[6];
    const float* w2         = (const float*)d_in[7];
    const float* w3         = (const float*)d_in[8];
    const float* attn_norm  = (const float*)d_in[9];
    const float* ffn_norm   = (const float*)d_in[10];
    const float* final_norm = (const float*)d_in[11];
    float* out = (float*)d_out;
    (void)in_sizes; (void)n_in; (void)out_size;

    float *p_h, *p_hn, *p_q, *p_k, *p_v, *p_ao, *p_f1, *p_f3;
    cudaGetSymbolAddress((void**)&p_h,  g_h);
    cudaGetSymbolAddress((void**)&p_hn, g_hn);
    cudaGetSymbolAddress((void**)&p_q,  g_q);
    cudaGetSymbolAddress((void**)&p_k,  g_k);
    cudaGetSymbolAddress((void**)&p_v,  g_v);
    cudaGetSymbolAddress((void**)&p_ao, g_ao);
    cudaGetSymbolAddress((void**)&p_f1, g_f1);
    cudaGetSymbolAddress((void**)&p_f3, g_f3);

    cudaFuncSetAttribute(attn_fused_kernel, cudaFuncAttributeMaxDynamicSharedMemorySize, ATTN_SMEM_BYTES);

    rope_tables_kernel<<<(SS*(HD/2)+255)/256, 256>>>();
    embed_kernel<<<(MROWS*DD+255)/256, 256>>>(tokens, emb);

    for (int l = 0; l < LL; l++) {
        // attention block
        rmsnorm_kernel<<<MROWS, 256>>>(p_h, attn_norm + l*DD, p_hn);
        gemm_tf32x3_kernel<0,0><<<dim3(DD/128, MROWS/128), 256>>>(p_hn, wq + (size_t)l*DD*DD, p_q, MROWS, DD, DD);
        gemm_tf32x3_kernel<0,0><<<dim3(DD/128, MROWS/128), 256>>>(p_hn, wk + (size_t)l*DD*DD, p_k, MROWS, DD, DD);
        gemm_tf32x3_kernel<0,0><<<dim3(DD/128, MROWS/128), 256>>>(p_hn, wv + (size_t)l*DD*DD, p_v, MROWS, DD, DD);
        rope_kernel<<<(BB*SS*HH*(HD/2)+255)/256, 256>>>(p_q);
        rope_kernel<<<(BB*SS*HH*(HD/2)+255)/256, 256>>>(p_k);
        attn_fused_kernel<<<dim3(1, SS/64, BB*HH), 256, ATTN_SMEM_BYTES>>>();
        gemm_tf32x3_kernel<0,1><<<dim3(DD/128, MROWS/128), 256>>>(p_ao, wo + (size_t)l*DD*DD, p_h, MROWS, DD, DD);

        // FFN block
        rmsnorm_kernel<<<MROWS, 256>>>(p_h, ffn_norm + l*DD, p_hn);
        gemm_tf32x3_kernel<0,0><<<dim3(FFD/128, MROWS/128), 256>>>(p_hn, w1 + (size_t)l*DD*FFD, p_f1, MROWS, FFD, DD);
        gemm_tf32x3_kernel<0,0><<<dim3(FFD/128, MROWS/128), 256>>>(p_hn, w3 + (size_t)l*DD*FFD, p_f3, MROWS, FFD, DD);
        silu_mul_kernel<<<(MROWS*FFD+255)/256, 256>>>();
        gemm_tf32x3_kernel<0,1><<<dim3(DD/128, MROWS/128), 256>>>(p_f1, w2 + (size_t)l*FFD*DD, p_h, MROWS, DD, FFD);
    }

    rmsnorm_kernel<<<MROWS, 256>>>(p_h, final_norm, p_hn);
    gemm_tf32x1_nt_kernel<<<dim3(VV/128, MROWS/128), 256>>>(p_hn, emb, out, MROWS, VV, DD);
}

// round 13
// speedup vs baseline: 1.5844x; 1.1157x over previous
#include <cuda_runtime.h>
#include <math.h>

#define BB 2
#define SS 1024
#define DD 1024
#define HH 16
#define HD 64
#define LL 4
#define FFD 2816
#define VV 32000
#define MROWS (BB*SS)   // 2048
#define EPSV 1e-6f

// ---------------- scratch (device globals; no allocations) ----------------
__device__ float g_h  [MROWS*DD];
__device__ float g_hn [MROWS*DD];
__device__ float g_q  [MROWS*DD];
__device__ float g_k  [MROWS*DD];
__device__ float g_v  [MROWS*DD];
__device__ float g_ao [MROWS*DD];
__device__ float g_f1 [MROWS*FFD];
__device__ float g_f3 [MROWS*FFD];
__device__ float g_cos[SS*(HD/2)];
__device__ float g_sin[SS*(HD/2)];

// ---------------- small elementwise kernels ----------------
__global__ void rope_tables_kernel() {
    int idx = blockIdx.x*blockDim.x + threadIdx.x;
    if (idx >= SS*(HD/2)) return;
    int s = idx / (HD/2);
    int j = idx % (HD/2);
    float inv = powf(10000.0f, -2.0f*(float)j/(float)HD);
    float ang = (float)s * inv;
    g_cos[idx] = cosf(ang);
    g_sin[idx] = sinf(ang);
}

__global__ void embed_kernel(const int* __restrict__ tokens, const float* __restrict__ emb) {
    int idx = blockIdx.x*blockDim.x + threadIdx.x;
    if (idx >= MROWS*DD) return;
    int row = idx / DD;
    int d   = idx % DD;
    g_h[idx] = emb[(size_t)tokens[row]*DD + d];
}

__global__ void rope_kernel(float* __restrict__ x) {
    int idx = blockIdx.x*blockDim.x + threadIdx.x;
    const int total = BB*SS*HH*(HD/2);
    if (idx >= total) return;
    int j = idx % (HD/2);
    int h = (idx/(HD/2)) % HH;
    int s = (idx/(HD/2)/HH) % SS;
    int b =  idx/(HD/2)/HH/SS;
    float c  = g_cos[s*(HD/2)+j];
    float sn = g_sin[s*(HD/2)+j];
    size_t base = (size_t)(b*SS+s)*DD + h*HD + 2*j;
    float x0 = x[base], x1 = x[base+1];
    x[base]   = x0*c - x1*sn;
    x[base+1] = x0*sn + x1*c;
}

__global__ void rmsnorm_kernel(const float* __restrict__ x, const float* __restrict__ w,
                               float* __restrict__ out) {
    int row = blockIdx.x;
    int t   = threadIdx.x;
    const float* xr = x + (size_t)row*DD;
    float v[4];
    float ss = 0.f;
    #pragma unroll
    for (int e = 0; e < 4; e++) { v[e] = xr[t + e*256]; ss += v[e]*v[e]; }
    __shared__ float red[256];
    red[t] = ss; __syncthreads();
    for (int off = 128; off > 0; off >>= 1) {
        if (t < off) red[t] += red[t+off];
        __syncthreads();
    }
    float scale = rsqrtf(red[0]/(float)DD + EPSV);
    #pragma unroll
    for (int e = 0; e < 4; e++) {
        int d = t + e*256;
        out[(size_t)row*DD + d] = v[e]*scale*w[d];
    }
}

__global__ void silu_mul_kernel() {
    int idx = blockIdx.x*blockDim.x + threadIdx.x;
    if (idx >= MROWS*FFD) return;
    float a = g_f1[idx];
    float sig = 1.0f / (1.0f + __expf(-a));
    g_f1[idx] = a*sig*g_f3[idx];
}

// ---------------- TF32 helpers ----------------
__device__ __forceinline__ unsigned f2tf(float f) {
    unsigned u;
    asm("cvt.rna.tf32.f32 %0, %1;" : "=r"(u) : "f"(f));
    return u;
}
__device__ __forceinline__ void split_tf(float f, unsigned& hi, unsigned& lo) {
    hi = f2tf(f);
    lo = f2tf(f - __uint_as_float(hi));
}
__device__ __forceinline__ void mma_tf32(float* c, const unsigned* a, const unsigned* b) {
    asm volatile(
        "mma.sync.aligned.m16n8k8.row.col.f32.tf32.tf32.f32 "
        "{%0,%1,%2,%3}, {%4,%5,%6,%7}, {%8,%9}, {%0,%1,%2,%3};\n"
        : "+f"(c[0]), "+f"(c[1]), "+f"(c[2]), "+f"(c[3])
        : "r"(a[0]), "r"(a[1]), "r"(a[2]), "r"(a[3]), "r"(b[0]), "r"(b[1]));
}

#define PADW 136

// ---------------- 3xTF32 GEMM, multi-segment fused, templated M-tile ----------------
// Computes C_seg[M, NPER] = A[M,K] @ B_seg[K, NPER] for up to 3 (B,C) segments,
// selected by blockIdx.x. All B are row-major [K][NPER].
// MSUB = number of 16-row m-subtiles per warp (2 -> 128-row CTA tile, 1 -> 64-row).
// 8 warps 4(m)x2(n); warp tile (MSUB*16) x 64; m16n8k8 tf32, 3-MMA split products.
template<int MSUB, int ACC>
__global__ void __launch_bounds__(256, 2)
gemm_tf32x3_fused(const float* __restrict__ A,
                  const float* __restrict__ B0, const float* __restrict__ B1, const float* __restrict__ B2,
                  float* __restrict__ C0, float* __restrict__ C1, float* __restrict__ C2,
                  int NPER, int K) {
    const int MT = MSUB*64;                 // CTA tile rows
    const int APW = MSUB*64 + 8;            // A smem row width (padded)
    __shared__ float As[2][16][MSUB*64 + 8];
    __shared__ float Bs[2][16][PADW];

    int tid  = threadIdx.x;
    int lane = tid & 31;
    int gr   = lane >> 2;     // 0..7
    int tg   = lane & 3;      // 0..3
    int wid  = tid >> 5;      // 0..7
    int wm   = (wid >> 1) * (MSUB*16);
    int wn   = (wid & 1) * 64;

    int nseg_blocks = NPER >> 7;
    int which = blockIdx.x / nseg_blocks;
    int nblk  = blockIdx.x - which*nseg_blocks;
    const float* B = (which == 0) ? B0 : (which == 1) ? B1 : B2;
    float*       C = (which == 0) ? C0 : (which == 1) ? C1 : C2;
    int n0 = nblk << 7;
    int m0 = blockIdx.y * MT;

    float acc[MSUB][8][4];
    #pragma unroll
    for (int mi = 0; mi < MSUB; mi++)
        #pragma unroll
        for (int ni = 0; ni < 8; ni++)
            #pragma unroll
            for (int r = 0; r < 4; r++) acc[mi][ni][r] = 0.f;

    const int nk = K >> 4;

    // ---- prologue: chunk 0 -> buffer 0 ----
    {
        #pragma unroll
        for (int e = 0; e < MSUB; e++) {
            int idx = tid + e*256;
            int row = idx >> 2;              // 0..MT-1
            int kq  = (idx & 3) << 2;
            float4 a4 = *(const float4*)&A[(size_t)(m0+row)*K + kq];
            As[0][kq+0][row] = a4.x;
            As[0][kq+1][row] = a4.y;
            As[0][kq+2][row] = a4.z;
            As[0][kq+3][row] = a4.w;
        }
        #pragma unroll
        for (int e = 0; e < 2; e++) {
            int idx = tid + e*256;
            int k  = idx >> 5;
            int nq = (idx & 31) << 2;
            float4 b4 = *(const float4*)&B[(size_t)k*NPER + n0 + nq];
            *(float4*)&Bs[0][k][nq] = b4;
        }
    }
    __syncthreads();

    for (int kc = 0; kc < nk; kc++) {
        int buf = kc & 1;
        if (kc + 1 < nk) {
            int k0 = (kc + 1) << 4;
            int nb = buf ^ 1;
            #pragma unroll
            for (int e = 0; e < MSUB; e++) {
                int idx = tid + e*256;
                int row = idx >> 2;
                int kq  = (idx & 3) << 2;
                float4 a4 = *(const float4*)&A[(size_t)(m0+row)*K + k0 + kq];
                As[nb][kq+0][row] = a4.x;
                As[nb][kq+1][row] = a4.y;
                As[nb][kq+2][row] = a4.z;
                As[nb][kq+3][row] = a4.w;
            }
            #pragma unroll
            for (int e = 0; e < 2; e++) {
                int idx = tid + e*256;
                int k  = idx >> 5;
                int nq = (idx & 31) << 2;
                float4 b4 = *(const float4*)&B[(size_t)(k0+k)*NPER + n0 + nq];
                *(float4*)&Bs[nb][k][nq] = b4;
            }
        }

        #pragma unroll
        for (int ks = 0; ks < 2; ks++) {
            int kb = ks << 3;
            unsigned ah[MSUB][4], al[MSUB][4];
            #pragma unroll
            for (int mi = 0; mi < MSUB; mi++) {
                int mb = wm + mi*16;
                split_tf(As[buf][kb+tg  ][mb+gr  ], ah[mi][0], al[mi][0]);
                split_tf(As[buf][kb+tg  ][mb+gr+8], ah[mi][1], al[mi][1]);
                split_tf(As[buf][kb+tg+4][mb+gr  ], ah[mi][2], al[mi][2]);
                split_tf(As[buf][kb+tg+4][mb+gr+8], ah[mi][3], al[mi][3]);
            }
            #pragma unroll
            for (int ni = 0; ni < 8; ni++) {
                int nb2 = wn + ni*8 + gr;
                unsigned bh[2], bl[2];
                split_tf(Bs[buf][kb+tg  ][nb2], bh[0], bl[0]);
                split_tf(Bs[buf][kb+tg+4][nb2], bh[1], bl[1]);
                #pragma unroll
                for (int mi = 0; mi < MSUB; mi++) {
                    mma_tf32(acc[mi][ni], al[mi], bh);
                    mma_tf32(acc[mi][ni], ah[mi], bl);
                    mma_tf32(acc[mi][ni], ah[mi], bh);
                }
            }
        }
        __syncthreads();
    }

    // ---- epilogue ----
    #pragma unroll
    for (int mi = 0; mi < MSUB; mi++) {
        int r0 = m0 + wm + mi*16 + gr;
        #pragma unroll
        for (int ni = 0; ni < 8; ni++) {
            int c0 = n0 + wn + ni*8 + tg*2;
            float* p0 = &C[(size_t)r0*NPER + c0];
            float* p1 = &C[(size_t)(r0+8)*NPER + c0];
            if (ACC) {
                p0[0] += acc[mi][ni][0]; p0[1] += acc[mi][ni][1];
                p1[0] += acc[mi][ni][2]; p1[1] += acc[mi][ni][3];
            } else {
                p0[0] = acc[mi][ni][0]; p0[1] = acc[mi][ni][1];
                p1[0] = acc[mi][ni][2]; p1[1] = acc[mi][ni][3];
            }
        }
    }
    (void)APW;
}

// ---------------- pure TF32 GEMM (1 MMA), for the final logits only ----------------
// C[M,N] = A[M,K] @ B[N,K]^T. smem holds tf32-converted values; inner loop pure LDS+MMA.
__global__ void __launch_bounds__(256, 2)
gemm_tf32x1_nt_kernel(const float* __restrict__ A, const float* __restrict__ B,
                      float* __restrict__ C, int M, int N, int K) {
    __shared__ unsigned As[2][16][PADW];   // [k][m], tf32
    __shared__ unsigned Bs[2][16][PADW];   // [k][n], tf32

    int tid  = threadIdx.x;
    int lane = tid & 31;
    int gr   = lane >> 2;
    int tg   = lane & 3;
    int wid  = tid >> 5;
    int wm   = (wid >> 1) * 32;
    int wn   = (wid & 1) * 64;
    int m0   = blockIdx.y << 7;
    int n0   = blockIdx.x << 7;

    float acc[2][8][4];
    #pragma unroll
    for (int mi = 0; mi < 2; mi++)
        #pragma unroll
        for (int ni = 0; ni < 8; ni++)
            #pragma unroll
            for (int r = 0; r < 4; r++) acc[mi][ni][r] = 0.f;

    const int nk = K >> 4;

    // prologue
    {
        #pragma unroll
        for (int e = 0; e < 2; e++) {
            int idx = tid + e*256;
            int row = idx >> 2;
            int kq  = (idx & 3) << 2;
            float4 a4 = *(const float4*)&A[(size_t)(m0+row)*K + kq];
            As[0][kq+0][row] = f2tf(a4.x);
            As[0][kq+1][row] = f2tf(a4.y);
            As[0][kq+2][row] = f2tf(a4.z);
            As[0][kq+3][row] = f2tf(a4.w);
            float4 b4 = *(const float4*)&B[(size_t)(n0+row)*K + kq];
            Bs[0][kq+0][row] = f2tf(b4.x);
            Bs[0][kq+1][row] = f2tf(b4.y);
            Bs[0][kq+2][row] = f2tf(b4.z);
            Bs[0][kq+3][row] = f2tf(b4.w);
        }
    }
    __syncthreads();

    for (int kc = 0; kc < nk; kc++) {
        int buf = kc & 1;
        if (kc + 1 < nk) {
            int k0 = (kc + 1) << 4;
            int nb = buf ^ 1;
            #pragma unroll
            for (int e = 0; e < 2; e++) {
                int idx = tid + e*256;
                int row = idx >> 2;
                int kq  = (idx & 3) << 2;
                float4 a4 = *(const float4*)&A[(size_t)(m0+row)*K + k0 + kq];
                As[nb][kq+0][row] = f2tf(a4.x);
                As[nb][kq+1][row] = f2tf(a4.y);
                As[nb][kq+2][row] = f2tf(a4.z);
                As[nb][kq+3][row] = f2tf(a4.w);
                float4 b4 = *(const float4*)&B[(size_t)(n0+row)*K + k0 + kq];
                Bs[nb][kq+0][row] = f2tf(b4.x);
                Bs[nb][kq+1][row] = f2tf(b4.y);
                Bs[nb][kq+2][row] = f2tf(b4.z);
                Bs[nb][kq+3][row] = f2tf(b4.w);
            }
        }

        #pragma unroll
        for (int ks = 0; ks < 2; ks++) {
            int kb = ks << 3;
            unsigned a[2][4];
            #pragma unroll
            for (int mi = 0; mi < 2; mi++) {
                int mb = wm + mi*16;
                a[mi][0] = As[buf][kb+tg  ][mb+gr  ];
                a[mi][1] = As[buf][kb+tg  ][mb+gr+8];
                a[mi][2] = As[buf][kb+tg+4][mb+gr  ];
                a[mi][3] = As[buf][kb+tg+4][mb+gr+8];
            }
            #pragma unroll
            for (int ni = 0; ni < 8; ni++) {
                int nb2 = wn + ni*8 + gr;
                unsigned b[2];
                b[0] = Bs[buf][kb+tg  ][nb2];
                b[1] = Bs[buf][kb+tg+4][nb2];
                #pragma unroll
                for (int mi = 0; mi < 2; mi++)
                    mma_tf32(acc[mi][ni], a[mi], b);
            }
        }
        __syncthreads();
    }

    #pragma unroll
    for (int mi = 0; mi < 2; mi++) {
        int r0 = m0 + wm + mi*16 + gr;
        #pragma unroll
        for (int ni = 0; ni < 8; ni++) {
            int c0 = n0 + wn + ni*8 + tg*2;
            C[(size_t)r0*N + c0 + 0] = acc[mi][ni][0];
            C[(size_t)r0*N + c0 + 1] = acc[mi][ni][1];
            C[(size_t)(r0+8)*N + c0 + 0] = acc[mi][ni][2];
            C[(size_t)(r0+8)*N + c0 + 1] = acc[mi][ni][3];
        }
    }
}

// ---------------- fused flash attention ----------------
#define ATTN_SMEM_BYTES ((3*64*65 + 64*64) * 4)

__global__ void __launch_bounds__(256)
attn_fused_kernel() {
    extern __shared__ float sm[];
    float (*Qs)[65] = (float(*)[65])sm;
    float (*Ks)[65] = (float(*)[65])(sm + 64*65);
    float (*Ps)[65] = (float(*)[65])(sm + 2*64*65);
    float (*Vs)[64] = (float(*)[64])(sm + 3*64*65);

    int bh = blockIdx.z;
    int b = bh >> 4, h = bh & 15;
    int it = blockIdx.y;
    int i0 = it << 6;
    int tid = threadIdx.x;
    int tx = tid & 15, ty = tid >> 4;

    #pragma unroll
    for (int e = 0; e < 16; e++) {
        int lin = tid + e*256;
        int r = lin >> 6, c = lin & 63;
        Qs[r][c] = g_q[(size_t)(b*SS + i0 + r)*DD + h*HD + c];
    }

    float m_run[4], l_run[4], o[4][4];
    #pragma unroll
    for (int i = 0; i < 4; i++) {
        m_run[i] = -1e30f; l_run[i] = 0.f;
        #pragma unroll
        for (int j = 0; j < 4; j++) o[i][j] = 0.f;
    }

    for (int jt = 0; jt <= it; jt++) {
        int j0 = jt << 6;
        #pragma unroll
        for (int e = 0; e < 16; e++) {
            int lin = tid + e*256;
            int r = lin >> 6, c = lin & 63;
            Ks[r][c] = g_k[(size_t)(b*SS + j0 + r)*DD + h*HD + c];
            Vs[r][c] = g_v[(size_t)(b*SS + j0 + r)*DD + h*HD + c];
        }
        __syncthreads();

        float s[4][4] = {};
        #pragma unroll 8
        for (int kk = 0; kk < 64; kk++) {
            float a[4], bb[4];
            #pragma unroll
            for (int i = 0; i < 4; i++) a[i]  = Qs[ty*4+i][kk];
            #pragma unroll
            for (int j = 0; j < 4; j++) bb[j] = Ks[tx*4+j][kk];
            #pragma unroll
            for (int i = 0; i < 4; i++)
                #pragma unroll
                for (int j = 0; j < 4; j++)
                    s[i][j] += a[i]*bb[j];
        }

        #pragma unroll
        for (int i = 0; i < 4; i++) {
            int gi = i0 + ty*4 + i;
            #pragma unroll
            for (int j = 0; j < 4; j++) {
                int gj = j0 + tx*4 + j;
                s[i][j] = (gj > gi) ? -1e30f : s[i][j]*0.125f;
            }
        }

        #pragma unroll
        for (int i = 0; i < 4; i++) {
            float mloc = fmaxf(fmaxf(s[i][0], s[i][1]), fmaxf(s[i][2], s[i][3]));
            #pragma unroll
            for (int off = 8; off > 0; off >>= 1)
                mloc = fmaxf(mloc, __shfl_xor_sync(0xffffffffu, mloc, off));
            float m_new = fmaxf(m_run[i], mloc);
            float corr = __expf(m_run[i] - m_new);
            l_run[i] *= corr;
            #pragma unroll
            for (int j = 0; j < 4; j++) o[i][j] *= corr;
            float rs = 0.f;
            #pragma unroll
            for (int j = 0; j < 4; j++) {
                s[i][j] = __expf(s[i][j] - m_new);
                rs += s[i][j];
            }
            #pragma unroll
            for (int off = 8; off > 0; off >>= 1)
                rs += __shfl_xor_sync(0xffffffffu, rs, off);
            l_run[i] += rs;
            m_run[i] = m_new;
        }

        #pragma unroll
        for (int i = 0; i < 4; i++)
            #pragma unroll
            for (int j = 0; j < 4; j++)
                Ps[ty*4+i][tx*4+j] = s[i][j];
        __syncthreads();

        #pragma unroll 8
        for (int kk = 0; kk < 64; kk++) {
            float a[4];
            #pragma unroll
            for (int i = 0; i < 4; i++) a[i] = Ps[ty*4+i][kk];
            float4 v4 = *(const float4*)&Vs[kk][tx*4];
            float bv[4] = {v4.x, v4.y, v4.z, v4.w};
            #pragma unroll
            for (int i = 0; i < 4; i++)
                #pragma unroll
                for (int j = 0; j < 4; j++)
                    o[i][j] += a[i]*bv[j];
        }
        __syncthreads();
    }

    #pragma unroll
    for (int i = 0; i < 4; i++) {
        float inv = 1.0f / l_run[i];
        #pragma unroll
        for (int j = 0; j < 4; j++)
            g_ao[(size_t)(b*SS + i0 + ty*4 + i)*DD + h*HD + tx*4 + j] = o[i][j]*inv;
    }
}

// ---------------- host launcher ----------------
extern "C" void kernel_launch(void* const* d_in, const int* in_sizes, int n_in,
                              void* d_out, int out_size) {
    const int*   tokens     = (const int*)  d_in[0];
    const float* emb        = (const float*)d_in[1];
    const float* wq         = (const float*)d_in[2];
    const float* wk         = (const float*)d_in[3];
    const float* wv         = (const float*)d_in[4];
    const float* wo         = (const float*)d_in[5];
    const float* w1         = (const float*)d_in[6];
    const float* w2         = (const float*)d_in[7];
    const float* w3         = (const float*)d_in[8];
    const float* attn_norm  = (const float*)d_in[9];
    const float* ffn_norm   = (const float*)d_in[10];
    const float* final_norm = (const float*)d_in[11];
    float* out = (float*)d_out;
    (void)in_sizes; (void)n_in; (void)out_size;

    float *p_h, *p_hn, *p_q, *p_k, *p_v, *p_ao, *p_f1, *p_f3;
    cudaGetSymbolAddress((void**)&p_h,  g_h);
    cudaGetSymbolAddress((void**)&p_hn, g_hn);
    cudaGetSymbolAddress((void**)&p_q,  g_q);
    cudaGetSymbolAddress((void**)&p_k,  g_k);
    cudaGetSymbolAddress((void**)&p_v,  g_v);
    cudaGetSymbolAddress((void**)&p_ao, g_ao);
    cudaGetSymbolAddress((void**)&p_f1, g_f1);
    cudaGetSymbolAddress((void**)&p_f3, g_f3);

    cudaFuncSetAttribute(attn_fused_kernel, cudaFuncAttributeMaxDynamicSharedMemorySize, ATTN_SMEM_BYTES);

    rope_tables_kernel<<<(SS*(HD/2)+255)/256, 256>>>();
    embed_kernel<<<(MROWS*DD+255)/256, 256>>>(tokens, emb);

    for (int l = 0; l < LL; l++) {
        // attention block
        rmsnorm_kernel<<<MROWS, 256>>>(p_h, attn_norm + l*DD, p_hn);
        // fused QKV: 3 segments of N=DD -> grid 24 x 16 = 384 CTAs
        gemm_tf32x3_fused<2,0><<<dim3(3*(DD/128), MROWS/128), 256>>>(
            p_hn, wq + (size_t)l*DD*DD, wk + (size_t)l*DD*DD, wv + (size_t)l*DD*DD,
            p_q, p_k, p_v, DD, DD);
        rope_kernel<<<(BB*SS*HH*(HD/2)+255)/256, 256>>>(p_q);
        rope_kernel<<<(BB*SS*HH*(HD/2)+255)/256, 256>>>(p_k);
        attn_fused_kernel<<<dim3(1, SS/64, BB*HH), 256, ATTN_SMEM_BYTES>>>();
        // WO (accumulate into h): 64-row tiles -> grid 8 x 32 = 256 CTAs
        gemm_tf32x3_fused<1,1><<<dim3(DD/128, MROWS/64), 256>>>(
            p_ao, wo + (size_t)l*DD*DD, 0, 0, p_h, 0, 0, DD, DD);

        // FFN block
        rmsnorm_kernel<<<MROWS, 256>>>(p_h, ffn_norm + l*DD, p_hn);
        // fused W1+W3: 2 segments of N=FFD -> grid 44 x 16 = 704 CTAs
        gemm_tf32x3_fused<2,0><<<dim3(2*(FFD/128), MROWS/128), 256>>>(
            p_hn, w1 + (size_t)l*DD*FFD, w3 + (size_t)l*DD*FFD, 0,
            p_f1, p_f3, 0, FFD, DD);
        silu_mul_kernel<<<(MROWS*FFD+255)/256, 256>>>();
        // W2 (accumulate into h): 64-row tiles -> grid 8 x 32 = 256 CTAs
        gemm_tf32x3_fused<1,1><<<dim3(DD/128, MROWS/64), 256>>>(
            p_f1, w2 + (size_t)l*FFD*DD, 0, 0, p_h, 0, 0, DD, FFD);
    }

    rmsnorm_kernel<<<MROWS, 256>>>(p_h, final_norm, p_hn);
    gemm_tf32x1_nt_kernel<<<dim3(VV/128, MROWS/128), 256>>>(p_hn, emb, out, MROWS, VV, DD);
}

// round 15
// speedup vs baseline: 1.7966x; 1.1340x over previous
#include <cuda_runtime.h>
#include <math.h>

#define BB 2
#define SS 1024
#define DD 1024
#define HH 16
#define HD 64
#define LL 4
#define FFD 2816
#define VV 32000
#define MROWS (BB*SS)   // 2048
#define EPSV 1e-6f

// ---------------- scratch (device globals; no allocations) ----------------
__device__ float g_h  [MROWS*DD];
__device__ float g_hn [MROWS*DD];
__device__ float g_q  [MROWS*DD];
__device__ float g_k  [MROWS*DD];
__device__ float g_v  [MROWS*DD];
__device__ float g_ao [MROWS*DD];
__device__ float g_f1 [MROWS*FFD];
__device__ float g_f3 [MROWS*FFD];
__device__ float g_cos[SS*(HD/2)];
__device__ float g_sin[SS*(HD/2)];

// ---------------- small elementwise kernels ----------------
__global__ void rope_tables_kernel() {
    int idx = blockIdx.x*blockDim.x + threadIdx.x;
    if (idx >= SS*(HD/2)) return;
    int s = idx / (HD/2);
    int j = idx % (HD/2);
    float inv = powf(10000.0f, -2.0f*(float)j/(float)HD);
    float ang = (float)s * inv;
    g_cos[idx] = cosf(ang);
    g_sin[idx] = sinf(ang);
}

__global__ void embed_kernel(const int* __restrict__ tokens, const float* __restrict__ emb) {
    int idx = blockIdx.x*blockDim.x + threadIdx.x;
    if (idx >= MROWS*DD) return;
    int row = idx / DD;
    int d   = idx % DD;
    g_h[idx] = emb[(size_t)tokens[row]*DD + d];
}

__global__ void rope_kernel(float* __restrict__ x) {
    int idx = blockIdx.x*blockDim.x + threadIdx.x;
    const int total = BB*SS*HH*(HD/2);
    if (idx >= total) return;
    int j = idx % (HD/2);
    int h = (idx/(HD/2)) % HH;
    int s = (idx/(HD/2)/HH) % SS;
    int b =  idx/(HD/2)/HH/SS;
    float c  = g_cos[s*(HD/2)+j];
    float sn = g_sin[s*(HD/2)+j];
    size_t base = (size_t)(b*SS+s)*DD + h*HD + 2*j;
    float x0 = x[base], x1 = x[base+1];
    x[base]   = x0*c - x1*sn;
    x[base+1] = x0*sn + x1*c;
}

__global__ void rmsnorm_kernel(const float* __restrict__ x, const float* __restrict__ w,
                               float* __restrict__ out) {
    int row = blockIdx.x;
    int t   = threadIdx.x;
    const float* xr = x + (size_t)row*DD;
    float v[4];
    float ss = 0.f;
    #pragma unroll
    for (int e = 0; e < 4; e++) { v[e] = xr[t + e*256]; ss += v[e]*v[e]; }
    __shared__ float red[256];
    red[t] = ss; __syncthreads();
    for (int off = 128; off > 0; off >>= 1) {
        if (t < off) red[t] += red[t+off];
        __syncthreads();
    }
    float scale = rsqrtf(red[0]/(float)DD + EPSV);
    #pragma unroll
    for (int e = 0; e < 4; e++) {
        int d = t + e*256;
        out[(size_t)row*DD + d] = v[e]*scale*w[d];
    }
}

__global__ void silu_mul_kernel() {
    int idx = blockIdx.x*blockDim.x + threadIdx.x;
    if (idx >= MROWS*FFD) return;
    float a = g_f1[idx];
    float sig = 1.0f / (1.0f + __expf(-a));
    g_f1[idx] = a*sig*g_f3[idx];
}

// ---------------- TF32 helpers ----------------
__device__ __forceinline__ unsigned f2tf(float f) {
    unsigned u;
    asm("cvt.rna.tf32.f32 %0, %1;" : "=r"(u) : "f"(f));
    return u;
}
// cheap exact split: hi = truncate-to-tf32 (exact tf32 bit pattern), lo = exact residual.
__device__ __forceinline__ void split_tf(float f, unsigned& hi, unsigned& lo) {
    unsigned u = __float_as_uint(f) & 0xFFFFE000u;
    hi = u;
    lo = __float_as_uint(f - __uint_as_float(u));
}
__device__ __forceinline__ void mma_tf32(float* c, const unsigned* a, const unsigned* b) {
    asm volatile(
        "mma.sync.aligned.m16n8k8.row.col.f32.tf32.tf32.f32 "
        "{%0,%1,%2,%3}, {%4,%5,%6,%7}, {%8,%9}, {%0,%1,%2,%3};\n"
        : "+f"(c[0]), "+f"(c[1]), "+f"(c[2]), "+f"(c[3])
        : "r"(a[0]), "r"(a[1]), "r"(a[2]), "r"(a[3]), "r"(b[0]), "r"(b[1]));
}

__device__ __forceinline__ unsigned smem_u32(const void* p) {
    return (unsigned)__cvta_generic_to_shared(p);
}
__device__ __forceinline__ void cp16(unsigned s, const void* g) {
    asm volatile("cp.async.cg.shared.global [%0], [%1], 16;" :: "r"(s), "l"(g));
}
#define CP_COMMIT() asm volatile("cp.async.commit_group;")

#define PADW 136
#define AKW  20     // A smem row width: 16 k-floats + 4 pad (stride 20 -> conflict-free frags)

// ---------------- 3xTF32 GEMM, cp.async 3-stage, multi-segment fused ----------------
// C_seg[M, NPER] = A[M,K] @ B_seg[K, NPER], up to 3 segments selected by blockIdx.x.
// A smem: [stage][m][AKW] raw fp32; B smem: [stage][k][PADW] raw fp32.
// MSUB: 16-row m-subtiles per warp (2 -> 128-row CTA tile, 1 -> 64).
template<int MSUB, int ACC>
__global__ void __launch_bounds__(256, 2)
gemm_tf32x3_fused(const float* __restrict__ A,
                  const float* __restrict__ B0, const float* __restrict__ B1, const float* __restrict__ B2,
                  float* __restrict__ C0, float* __restrict__ C1, float* __restrict__ C2,
                  int NPER, int K) {
    const int MT  = MSUB*64;
    const int AST = MT*AKW;       // A stage floats
    const int BST = 16*PADW;      // B stage floats
    extern __shared__ float sm[];
    float* As = sm;               // [3][MT][AKW]
    float* Bs = sm + 3*AST;       // [3][16][PADW]
    unsigned sa = smem_u32(As);
    unsigned sb = smem_u32(Bs);

    int tid  = threadIdx.x;
    int lane = tid & 31;
    int gr   = lane >> 2;     // 0..7
    int tg   = lane & 3;      // 0..3
    int wid  = tid >> 5;      // 0..7
    int wm   = (wid >> 1) * (MSUB*16);
    int wn   = (wid & 1) * 64;

    int nseg_blocks = NPER >> 7;
    int which = blockIdx.x / nseg_blocks;
    int nblk  = blockIdx.x - which*nseg_blocks;
    const float* B = (which == 0) ? B0 : (which == 1) ? B1 : B2;
    float*       C = (which == 0) ? C0 : (which == 1) ? C1 : C2;
    int n0 = nblk << 7;
    int m0 = blockIdx.y * MT;

    float acc[MSUB][8][4];
    #pragma unroll
    for (int mi = 0; mi < MSUB; mi++)
        #pragma unroll
        for (int ni = 0; ni < 8; ni++)
            #pragma unroll
            for (int r = 0; r < 4; r++) acc[mi][ni][r] = 0.f;

    const int nk = K >> 4;

    // per-thread staging coords (fixed)
    int a_row = (tid & 1023) >> 2;           // used with e offsets below
    int a_kq  = (tid & 3) << 2;
    int b_k   = tid >> 5;
    int b_nq  = (tid & 31) << 2;
    (void)a_row;

    // stage chunk kc into ring slot st
    auto stage = [&](int kc, int st) {
        int k0 = kc << 4;
        #pragma unroll
        for (int e = 0; e < MSUB; e++) {
            int idx = tid + e*256;
            int row = idx >> 2;
            int kq  = (idx & 3) << 2;
            cp16(sa + (unsigned)(st*AST + row*AKW + kq)*4u,
                 &A[(size_t)(m0+row)*K + k0 + kq]);
        }
        #pragma unroll
        for (int e = 0; e < 2; e++) {
            int idx = tid + e*256;
            int k  = idx >> 5;
            int nq = (idx & 31) << 2;
            cp16(sb + (unsigned)(st*BST + k*PADW + nq)*4u,
                 &B[(size_t)(k0+k)*NPER + n0 + nq]);
        }
        CP_COMMIT();
    };
    (void)b_k; (void)b_nq; (void)a_kq;

    // prologue: stages 0 and 1 in flight
    stage(0, 0);
    stage(1, 1);

    for (int kc = 0; kc < nk; kc++) {
        int st = kc % 3;
        if (kc + 2 < nk) {
            asm volatile("cp.async.wait_group 1;" ::: "memory");
        } else {
            asm volatile("cp.async.wait_group 0;" ::: "memory");
        }
        __syncthreads();   // stage kc resident everywhere; all warps done with stage (kc+2)%3's old data
        if (kc + 2 < nk) stage(kc + 2, (kc + 2) % 3);

        const float* Ab = As + st*AST;
        const float* Bb = Bs + st*BST;
        #pragma unroll
        for (int ks = 0; ks < 2; ks++) {
            int kb = ks << 3;
            unsigned ah[MSUB][4], al[MSUB][4];
            #pragma unroll
            for (int mi = 0; mi < MSUB; mi++) {
                int mb = wm + mi*16;
                split_tf(Ab[(mb+gr  )*AKW + kb+tg  ], ah[mi][0], al[mi][0]);
                split_tf(Ab[(mb+gr+8)*AKW + kb+tg  ], ah[mi][1], al[mi][1]);
                split_tf(Ab[(mb+gr  )*AKW + kb+tg+4], ah[mi][2], al[mi][2]);
                split_tf(Ab[(mb+gr+8)*AKW + kb+tg+4], ah[mi][3], al[mi][3]);
            }
            #pragma unroll
            for (int ni = 0; ni < 8; ni++) {
                int nb2 = wn + ni*8 + gr;
                unsigned bh[2], bl[2];
                split_tf(Bb[(kb+tg  )*PADW + nb2], bh[0], bl[0]);
                split_tf(Bb[(kb+tg+4)*PADW + nb2], bh[1], bl[1]);
                #pragma unroll
                for (int mi = 0; mi < MSUB; mi++) {
                    mma_tf32(acc[mi][ni], al[mi], bh);
                    mma_tf32(acc[mi][ni], ah[mi], bl);
                    mma_tf32(acc[mi][ni], ah[mi], bh);
                }
            }
        }
    }

    __syncthreads();
    // ---- epilogue ----
    #pragma unroll
    for (int mi = 0; mi < MSUB; mi++) {
        int r0 = m0 + wm + mi*16 + gr;
        #pragma unroll
        for (int ni = 0; ni < 8; ni++) {
            int c0 = n0 + wn + ni*8 + tg*2;
            float* p0 = &C[(size_t)r0*NPER + c0];
            float* p1 = &C[(size_t)(r0+8)*NPER + c0];
            if (ACC) {
                p0[0] += acc[mi][ni][0]; p0[1] += acc[mi][ni][1];
                p1[0] += acc[mi][ni][2]; p1[1] += acc[mi][ni][3];
            } else {
                p0[0] = acc[mi][ni][0]; p0[1] = acc[mi][ni][1];
                p1[0] = acc[mi][ni][2]; p1[1] = acc[mi][ni][3];
            }
        }
    }
}

#define GEMM_SMEM(MSUB) ((3*((MSUB)*64*AKW) + 3*16*PADW) * 4)

// ---------------- pure TF32 GEMM (1 MMA), for the final logits only ----------------
// C[M,N] = A[M,K] @ B[N,K]^T. smem holds tf32-converted values; inner loop pure LDS+MMA.
__global__ void __launch_bounds__(256, 2)
gemm_tf32x1_nt_kernel(const float* __restrict__ A, const float* __restrict__ B,
                      float* __restrict__ C, int M, int N, int K) {
    __shared__ unsigned As[2][16][PADW];   // [k][m], tf32
    __shared__ unsigned Bs[2][16][PADW];   // [k][n], tf32

    int tid  = threadIdx.x;
    int lane = tid & 31;
    int gr   = lane >> 2;
    int tg   = lane & 3;
    int wid  = tid >> 5;
    int wm   = (wid >> 1) * 32;
    int wn   = (wid & 1) * 64;
    int m0   = blockIdx.y << 7;
    int n0   = blockIdx.x << 7;

    float acc[2][8][4];
    #pragma unroll
    for (int mi = 0; mi < 2; mi++)
        #pragma unroll
        for (int ni = 0; ni < 8; ni++)
            #pragma unroll
            for (int r = 0; r < 4; r++) acc[mi][ni][r] = 0.f;

    const int nk = K >> 4;

    // prologue
    {
        #pragma unroll
        for (int e = 0; e < 2; e++) {
            int idx = tid + e*256;
            int row = idx >> 2;
            int kq  = (idx & 3) << 2;
            float4 a4 = *(const float4*)&A[(size_t)(m0+row)*K + kq];
            As[0][kq+0][row] = f2tf(a4.x);
            As[0][kq+1][row] = f2tf(a4.y);
            As[0][kq+2][row] = f2tf(a4.z);
            As[0][kq+3][row] = f2tf(a4.w);
            float4 b4 = *(const float4*)&B[(size_t)(n0+row)*K + kq];
            Bs[0][kq+0][row] = f2tf(b4.x);
            Bs[0][kq+1][row] = f2tf(b4.y);
            Bs[0][kq+2][row] = f2tf(b4.z);
            Bs[0][kq+3][row] = f2tf(b4.w);
        }
    }
    __syncthreads();

    for (int kc = 0; kc < nk; kc++) {
        int buf = kc & 1;
        if (kc + 1 < nk) {
            int k0 = (kc + 1) << 4;
            int nb = buf ^ 1;
            #pragma unroll
            for (int e = 0; e < 2; e++) {
                int idx = tid + e*256;
                int row = idx >> 2;
                int kq  = (idx & 3) << 2;
                float4 a4 = *(const float4*)&A[(size_t)(m0+row)*K + k0 + kq];
                As[nb][kq+0][row] = f2tf(a4.x);
                As[nb][kq+1][row] = f2tf(a4.y);
                As[nb][kq+2][row] = f2tf(a4.z);
                As[nb][kq+3][row] = f2tf(a4.w);
                float4 b4 = *(const float4*)&B[(size_t)(n0+row)*K + k0 + kq];
                Bs[nb][kq+0][row] = f2tf(b4.x);
                Bs[nb][kq+1][row] = f2tf(b4.y);
                Bs[nb][kq+2][row] = f2tf(b4.z);
                Bs[nb][kq+3][row] = f2tf(b4.w);
            }
        }

        #pragma unroll
        for (int ks = 0; ks < 2; ks++) {
            int kb = ks << 3;
            unsigned a[2][4];
            #pragma unroll
            for (int mi = 0; mi < 2; mi++) {
                int mb = wm + mi*16;
                a[mi][0] = As[buf][kb+tg  ][mb+gr  ];
                a[mi][1] = As[buf][kb+tg  ][mb+gr+8];
                a[mi][2] = As[buf][kb+tg+4][mb+gr  ];
                a[mi][3] = As[buf][kb+tg+4][mb+gr+8];
            }
            #pragma unroll
            for (int ni = 0; ni < 8; ni++) {
                int nb2 = wn + ni*8 + gr;
                unsigned b[2];
                b[0] = Bs[buf][kb+tg  ][nb2];
                b[1] = Bs[buf][kb+tg+4][nb2];
                #pragma unroll
                for (int mi = 0; mi < 2; mi++)
                    mma_tf32(acc[mi][ni], a[mi], b);
            }
        }
        __syncthreads();
    }

    #pragma unroll
    for (int mi = 0; mi < 2; mi++) {
        int r0 = m0 + wm + mi*16 + gr;
        #pragma unroll
        for (int ni = 0; ni < 8; ni++) {
            int c0 = n0 + wn + ni*8 + tg*2;
            C[(size_t)r0*N + c0 + 0] = acc[mi][ni][0];
            C[(size_t)r0*N + c0 + 1] = acc[mi][ni][1];
            C[(size_t)(r0+8)*N + c0 + 0] = acc[mi][ni][2];
            C[(size_t)(r0+8)*N + c0 + 1] = acc[mi][ni][3];
        }
    }
}

// ---------------- fused flash attention ----------------
#define ATTN_SMEM_BYTES ((3*64*65 + 64*64) * 4)

__global__ void __launch_bounds__(256)
attn_fused_kernel() {
    extern __shared__ float sm[];
    float (*Qs)[65] = (float(*)[65])sm;
    float (*Ks)[65] = (float(*)[65])(sm + 64*65);
    float (*Ps)[65] = (float(*)[65])(sm + 2*64*65);
    float (*Vs)[64] = (float(*)[64])(sm + 3*64*65);

    int bh = blockIdx.z;
    int b = bh >> 4, h = bh & 15;
    int it = blockIdx.y;
    int i0 = it << 6;
    int tid = threadIdx.x;
    int tx = tid & 15, ty = tid >> 4;

    #pragma unroll
    for (int e = 0; e < 16; e++) {
        int lin = tid + e*256;
        int r = lin >> 6, c = lin & 63;
        Qs[r][c] = g_q[(size_t)(b*SS + i0 + r)*DD + h*HD + c];
    }

    float m_run[4], l_run[4], o[4][4];
    #pragma unroll
    for (int i = 0; i < 4; i++) {
        m_run[i] = -1e30f; l_run[i] = 0.f;
        #pragma unroll
        for (int j = 0; j < 4; j++) o[i][j] = 0.f;
    }

    for (int jt = 0; jt <= it; jt++) {
        int j0 = jt << 6;
        #pragma unroll
        for (int e = 0; e < 16; e++) {
            int lin = tid + e*256;
            int r = lin >> 6, c = lin & 63;
            Ks[r][c] = g_k[(size_t)(b*SS + j0 + r)*DD + h*HD + c];
            Vs[r][c] = g_v[(size_t)(b*SS + j0 + r)*DD + h*HD + c];
        }
        __syncthreads();

        float s[4][4] = {};
        #pragma unroll 8
        for (int kk = 0; kk < 64; kk++) {
            float a[4], bb[4];
            #pragma unroll
            for (int i = 0; i < 4; i++) a[i]  = Qs[ty*4+i][kk];
            #pragma unroll
            for (int j = 0; j < 4; j++) bb[j] = Ks[tx*4+j][kk];
            #pragma unroll
            for (int i = 0; i < 4; i++)
                #pragma unroll
                for (int j = 0; j < 4; j++)
                    s[i][j] += a[i]*bb[j];
        }

        #pragma unroll
        for (int i = 0; i < 4; i++) {
            int gi = i0 + ty*4 + i;
            #pragma unroll
            for (int j = 0; j < 4; j++) {
                int gj = j0 + tx*4 + j;
                s[i][j] = (gj > gi) ? -1e30f : s[i][j]*0.125f;
            }
        }

        #pragma unroll
        for (int i = 0; i < 4; i++) {
            float mloc = fmaxf(fmaxf(s[i][0], s[i][1]), fmaxf(s[i][2], s[i][3]));
            #pragma unroll
            for (int off = 8; off > 0; off >>= 1)
                mloc = fmaxf(mloc, __shfl_xor_sync(0xffffffffu, mloc, off));
            float m_new = fmaxf(m_run[i], mloc);
            float corr = __expf(m_run[i] - m_new);
            l_run[i] *= corr;
            #pragma unroll
            for (int j = 0; j < 4; j++) o[i][j] *= corr;
            float rs = 0.f;
            #pragma unroll
            for (int j = 0; j < 4; j++) {
                s[i][j] = __expf(s[i][j] - m_new);
                rs += s[i][j];
            }
            #pragma unroll
            for (int off = 8; off > 0; off >>= 1)
                rs += __shfl_xor_sync(0xffffffffu, rs, off);
            l_run[i] += rs;
            m_run[i] = m_new;
        }

        #pragma unroll
        for (int i = 0; i < 4; i++)
            #pragma unroll
            for (int j = 0; j < 4; j++)
                Ps[ty*4+i][tx*4+j] = s[i][j];
        __syncthreads();

        #pragma unroll 8
        for (int kk = 0; kk < 64; kk++) {
            float a[4];
            #pragma unroll
            for (int i = 0; i < 4; i++) a[i] = Ps[ty*4+i][kk];
            float4 v4 = *(const float4*)&Vs[kk][tx*4];
            float bv[4] = {v4.x, v4.y, v4.z, v4.w};
            #pragma unroll
            for (int i = 0; i < 4; i++)
                #pragma unroll
                for (int j = 0; j < 4; j++)
                    o[i][j] += a[i]*bv[j];
        }
        __syncthreads();
    }

    #pragma unroll
    for (int i = 0; i < 4; i++) {
        float inv = 1.0f / l_run[i];
        #pragma unroll
        for (int j = 0; j < 4; j++)
            g_ao[(size_t)(b*SS + i0 + ty*4 + i)*DD + h*HD + tx*4 + j] = o[i][j]*inv;
    }
}

// ---------------- host launcher ----------------
extern "C" void kernel_launch(void* const* d_in, const int* in_sizes, int n_in,
                              void* d_out, int out_size) {
    const int*   tokens     = (const int*)  d_in[0];
    const float* emb        = (const float*)d_in[1];
    const float* wq         = (const float*)d_in[2];
    const float* wk         = (const float*)d_in[3];
    const float* wv         = (const float*)d_in[4];
    const float* wo         = (const float*)d_in[5];
    const float* w1         = (const float*)d_in[6];
    const float* w2         = (const float*)d_in[7];
    const float* w3         = (const float*)d_in[8];
    const float* attn_norm  = (const float*)d_in[9];
    const float* ffn_norm   = (const float*)d_in[10];
    const float* final_norm = (const float*)d_in[11];
    float* out = (float*)d_out;
    (void)in_sizes; (void)n_in; (void)out_size;

    float *p_h, *p_hn, *p_q, *p_k, *p_v, *p_ao, *p_f1, *p_f3;
    cudaGetSymbolAddress((void**)&p_h,  g_h);
    cudaGetSymbolAddress((void**)&p_hn, g_hn);
    cudaGetSymbolAddress((void**)&p_q,  g_q);
    cudaGetSymbolAddress((void**)&p_k,  g_k);
    cudaGetSymbolAddress((void**)&p_v,  g_v);
    cudaGetSymbolAddress((void**)&p_ao, g_ao);
    cudaGetSymbolAddress((void**)&p_f1, g_f1);
    cudaGetSymbolAddress((void**)&p_f3, g_f3);

    cudaFuncSetAttribute(attn_fused_kernel, cudaFuncAttributeMaxDynamicSharedMemorySize, ATTN_SMEM_BYTES);
    cudaFuncSetAttribute(gemm_tf32x3_fused<2,0>, cudaFuncAttributeMaxDynamicSharedMemorySize, GEMM_SMEM(2));
    cudaFuncSetAttribute(gemm_tf32x3_fused<1,1>, cudaFuncAttributeMaxDynamicSharedMemorySize, GEMM_SMEM(1));

    rope_tables_kernel<<<(SS*(HD/2)+255)/256, 256>>>();
    embed_kernel<<<(MROWS*DD+255)/256, 256>>>(tokens, emb);

    for (int l = 0; l < LL; l++) {
        // attention block
        rmsnorm_kernel<<<MROWS, 256>>>(p_h, attn_norm + l*DD, p_hn);
        // fused QKV: 3 segments of N=DD -> grid 24 x 16 = 384 CTAs
        gemm_tf32x3_fused<2,0><<<dim3(3*(DD/128), MROWS/128), 256, GEMM_SMEM(2)>>>(
            p_hn, wq + (size_t)l*DD*DD, wk + (size_t)l*DD*DD, wv + (size_t)l*DD*DD,
            p_q, p_k, p_v, DD, DD);
        rope_kernel<<<(BB*SS*HH*(HD/2)+255)/256, 256>>>(p_q);
        rope_kernel<<<(BB*SS*HH*(HD/2)+255)/256, 256>>>(p_k);
        attn_fused_kernel<<<dim3(1, SS/64, BB*HH), 256, ATTN_SMEM_BYTES>>>();
        // WO (accumulate into h): 64-row tiles -> grid 8 x 32 = 256 CTAs
        gemm_tf32x3_fused<1,1><<<dim3(DD/128, MROWS/64), 256, GEMM_SMEM(1)>>>(
            p_ao, wo + (size_t)l*DD*DD, 0, 0, p_h, 0, 0, DD, DD);

        // FFN block
        rmsnorm_kernel<<<MROWS, 256>>>(p_h, ffn_norm + l*DD, p_hn);
        // fused W1+W3: 2 segments of N=FFD -> grid 44 x 16 = 704 CTAs
        gemm_tf32x3_fused<2,0><<<dim3(2*(FFD/128), MROWS/128), 256, GEMM_SMEM(2)>>>(
            p_hn, w1 + (size_t)l*DD*FFD, w3 + (size_t)l*DD*FFD, 0,
            p_f1, p_f3, 0, FFD, DD);
        silu_mul_kernel<<<(MROWS*FFD+255)/256, 256>>>();
        // W2 (accumulate into h): 64-row tiles -> grid 8 x 32 = 256 CTAs
        gemm_tf32x3_fused<1,1><<<dim3(DD/128, MROWS/64), 256, GEMM_SMEM(1)>>>(
            p_f1, w2 + (size_t)l*FFD*DD, 0, 0, p_h, 0, 0, DD, FFD);
    }

    rmsnorm_kernel<<<MROWS, 256>>>(p_h, final_norm, p_hn);
    gemm_tf32x1_nt_kernel<<<dim3(VV/128, MROWS/128), 256>>>(p_hn, emb, out, MROWS, VV, DD);
}

// round 17
// speedup vs baseline: 1.9132x; 1.0649x over previous
#include <cuda_runtime.h>
#include <math.h>

#define BB 2
#define SS 1024
#define DD 1024
#define HH 16
#define HD 64
#define LL 4
#define FFD 2816
#define VV 32000
#define MROWS (BB*SS)   // 2048
#define EPSV 1e-6f

// ---------------- scratch (device globals; no allocations) ----------------
__device__ float g_h  [MROWS*DD];
__device__ float g_hn [MROWS*DD];
__device__ float g_q  [MROWS*DD];
__device__ float g_k  [MROWS*DD];
__device__ float g_v  [MROWS*DD];
__device__ float g_ao [MROWS*DD];
__device__ float g_f1 [MROWS*FFD];
__device__ float g_f3 [MROWS*FFD];
__device__ float g_cos[SS*(HD/2)];
__device__ float g_sin[SS*(HD/2)];

// ---------------- small elementwise kernels ----------------
__global__ void rope_tables_kernel() {
    int idx = blockIdx.x*blockDim.x + threadIdx.x;
    if (idx >= SS*(HD/2)) return;
    int s = idx / (HD/2);
    int j = idx % (HD/2);
    float inv = powf(10000.0f, -2.0f*(float)j/(float)HD);
    float ang = (float)s * inv;
    g_cos[idx] = cosf(ang);
    g_sin[idx] = sinf(ang);
}

__global__ void embed_kernel(const int* __restrict__ tokens, const float* __restrict__ emb) {
    int idx = blockIdx.x*blockDim.x + threadIdx.x;
    if (idx >= MROWS*DD) return;
    int row = idx / DD;
    int d   = idx % DD;
    g_h[idx] = emb[(size_t)tokens[row]*DD + d];
}

__global__ void rope_kernel(float* __restrict__ x) {
    int idx = blockIdx.x*blockDim.x + threadIdx.x;
    const int total = BB*SS*HH*(HD/2);
    if (idx >= total) return;
    int j = idx % (HD/2);
    int h = (idx/(HD/2)) % HH;
    int s = (idx/(HD/2)/HH) % SS;
    int b =  idx/(HD/2)/HH/SS;
    float c  = g_cos[s*(HD/2)+j];
    float sn = g_sin[s*(HD/2)+j];
    size_t base = (size_t)(b*SS+s)*DD + h*HD + 2*j;
    float x0 = x[base], x1 = x[base+1];
    x[base]   = x0*c - x1*sn;
    x[base+1] = x0*sn + x1*c;
}

__global__ void rmsnorm_kernel(const float* __restrict__ x, const float* __restrict__ w,
                               float* __restrict__ out) {
    int row = blockIdx.x;
    int t   = threadIdx.x;
    const float* xr = x + (size_t)row*DD;
    float v[4];
    float ss = 0.f;
    #pragma unroll
    for (int e = 0; e < 4; e++) { v[e] = xr[t + e*256]; ss += v[e]*v[e]; }
    __shared__ float red[256];
    red[t] = ss; __syncthreads();
    for (int off = 128; off > 0; off >>= 1) {
        if (t < off) red[t] += red[t+off];
        __syncthreads();
    }
    float scale = rsqrtf(red[0]/(float)DD + EPSV);
    #pragma unroll
    for (int e = 0; e < 4; e++) {
        int d = t + e*256;
        out[(size_t)row*DD + d] = v[e]*scale*w[d];
    }
}

__global__ void silu_mul_kernel() {
    int idx = blockIdx.x*blockDim.x + threadIdx.x;
    if (idx >= MROWS*FFD) return;
    float a = g_f1[idx];
    float sig = 1.0f / (1.0f + __expf(-a));
    g_f1[idx] = a*sig*g_f3[idx];
}

// ---------------- TF32 helpers ----------------
__device__ __forceinline__ unsigned f2tf(float f) {
    unsigned u;
    asm("cvt.rna.tf32.f32 %0, %1;" : "=r"(u) : "f"(f));
    return u;
}
// cheap exact split: hi = truncate-to-tf32 (exact tf32 bit pattern), lo = exact residual.
__device__ __forceinline__ void split_tf(float f, unsigned& hi, unsigned& lo) {
    unsigned u = __float_as_uint(f) & 0xFFFFE000u;
    hi = u;
    lo = __float_as_uint(f - __uint_as_float(u));
}
__device__ __forceinline__ void mma_tf32(float* c, const unsigned* a, const unsigned* b) {
    asm volatile(
        "mma.sync.aligned.m16n8k8.row.col.f32.tf32.tf32.f32 "
        "{%0,%1,%2,%3}, {%4,%5,%6,%7}, {%8,%9}, {%0,%1,%2,%3};\n"
        : "+f"(c[0]), "+f"(c[1]), "+f"(c[2]), "+f"(c[3])
        : "r"(a[0]), "r"(a[1]), "r"(a[2]), "r"(a[3]), "r"(b[0]), "r"(b[1]));
}

__device__ __forceinline__ unsigned smem_u32(const void* p) {
    return (unsigned)__cvta_generic_to_shared(p);
}
__device__ __forceinline__ void cp16(unsigned s, const void* g) {
    asm volatile("cp.async.cg.shared.global [%0], [%1], 16;" :: "r"(s), "l"(g));
}
#define CP_COMMIT() asm volatile("cp.async.commit_group;")

#define PADW 136
#define AKW  20     // row-major smem tile width: 16 k-floats + 4 pad (conflict-free frags)

// ---------------- unified TF32 GEMM: cp.async 3-stage, fused segments ----------------
// C_seg[M, NPER] = A[M,K] @ op(B_seg); up to 3 segments selected by blockIdx.x.
// TRANSB=0: B row-major [K][NPER]; TRANSB=1: B row-major [NPER][K] (C = A @ B^T).
// NMMA=3: fp32-accurate 3xTF32 (truncation split). NMMA=1: pure TF32 (rna at frag load).
// MSUB: 16-row m-subtiles per warp (2 -> 128-row CTA tile, 1 -> 64).
template<int MSUB, int ACC, int TRANSB, int NMMA>
__global__ void __launch_bounds__(256, 2)
gemm_tf32_fused(const float* __restrict__ A,
                const float* __restrict__ B0, const float* __restrict__ B1, const float* __restrict__ B2,
                float* __restrict__ C0, float* __restrict__ C1, float* __restrict__ C2,
                int NPER, int K) {
    const int MT  = MSUB*64;
    const int AST = MT*AKW;                        // A stage floats
    const int BST = TRANSB ? 128*AKW : 16*PADW;    // B stage floats
    extern __shared__ float sm[];
    float* As = sm;               // [3][MT][AKW]
    float* Bs = sm + 3*AST;       // [3][...]
    unsigned sa = smem_u32(As);
    unsigned sb = smem_u32(Bs);

    int tid  = threadIdx.x;
    int lane = tid & 31;
    int gr   = lane >> 2;     // 0..7
    int tg   = lane & 3;      // 0..3
    int wid  = tid >> 5;      // 0..7
    int wm   = (wid >> 1) * (MSUB*16);
    int wn   = (wid & 1) * 64;

    int nseg_blocks = NPER >> 7;
    int which = blockIdx.x / nseg_blocks;
    int nblk  = blockIdx.x - which*nseg_blocks;
    const float* B = (which == 0) ? B0 : (which == 1) ? B1 : B2;
    float*       C = (which == 0) ? C0 : (which == 1) ? C1 : C2;
    int n0 = nblk << 7;
    int m0 = blockIdx.y * MT;

    float acc[MSUB][8][4];
    #pragma unroll
    for (int mi = 0; mi < MSUB; mi++)
        #pragma unroll
        for (int ni = 0; ni < 8; ni++)
            #pragma unroll
            for (int r = 0; r < 4; r++) acc[mi][ni][r] = 0.f;

    const int nk = K >> 4;

    // stage chunk kc into ring slot st
    auto stage = [&](int kc, int st) {
        int k0 = kc << 4;
        #pragma unroll
        for (int e = 0; e < MSUB; e++) {
            int idx = tid + e*256;
            int row = idx >> 2;
            int kq  = (idx & 3) << 2;
            cp16(sa + (unsigned)(st*AST + row*AKW + kq)*4u,
                 &A[(size_t)(m0+row)*K + k0 + kq]);
        }
        if (TRANSB) {
            #pragma unroll
            for (int e = 0; e < 2; e++) {
                int idx = tid + e*256;
                int row = idx >> 2;              // n-row 0..127
                int kq  = (idx & 3) << 2;
                cp16(sb + (unsigned)(st*BST + row*AKW + kq)*4u,
                     &B[(size_t)(n0+row)*K + k0 + kq]);
            }
        } else {
            #pragma unroll
            for (int e = 0; e < 2; e++) {
                int idx = tid + e*256;
                int k  = idx >> 5;
                int nq = (idx & 31) << 2;
                cp16(sb + (unsigned)(st*BST + k*PADW + nq)*4u,
                     &B[(size_t)(k0+k)*NPER + n0 + nq]);
            }
        }
        CP_COMMIT();
    };

    // prologue: stages 0 and 1 in flight
    stage(0, 0);
    stage(1, 1);

    for (int kc = 0; kc < nk; kc++) {
        int st = kc % 3;
        if (kc + 2 < nk) {
            asm volatile("cp.async.wait_group 1;" ::: "memory");
        } else {
            asm volatile("cp.async.wait_group 0;" ::: "memory");
        }
        __syncthreads();
        if (kc + 2 < nk) stage(kc + 2, (kc + 2) % 3);

        const float* Ab = As + st*AST;
        const float* Bb = Bs + st*BST;
        #pragma unroll
        for (int ks = 0; ks < 2; ks++) {
            int kb = ks << 3;
            if (NMMA == 3) {
                unsigned ah[MSUB][4], al[MSUB][4];
                #pragma unroll
                for (int mi = 0; mi < MSUB; mi++) {
                    int mb = wm + mi*16;
                    split_tf(Ab[(mb+gr  )*AKW + kb+tg  ], ah[mi][0], al[mi][0]);
                    split_tf(Ab[(mb+gr+8)*AKW + kb+tg  ], ah[mi][1], al[mi][1]);
                    split_tf(Ab[(mb+gr  )*AKW + kb+tg+4], ah[mi][2], al[mi][2]);
                    split_tf(Ab[(mb+gr+8)*AKW + kb+tg+4], ah[mi][3], al[mi][3]);
                }
                #pragma unroll
                for (int ni = 0; ni < 8; ni++) {
                    int nb2 = wn + ni*8 + gr;
                    unsigned bh[2], bl[2];
                    if (TRANSB) {
                        split_tf(Bb[nb2*AKW + kb+tg  ], bh[0], bl[0]);
                        split_tf(Bb[nb2*AKW + kb+tg+4], bh[1], bl[1]);
                    } else {
                        split_tf(Bb[(kb+tg  )*PADW + nb2], bh[0], bl[0]);
                        split_tf(Bb[(kb+tg+4)*PADW + nb2], bh[1], bl[1]);
                    }
                    #pragma unroll
                    for (int mi = 0; mi < MSUB; mi++) {
                        mma_tf32(acc[mi][ni], al[mi], bh);
                        mma_tf32(acc[mi][ni], ah[mi], bl);
                        mma_tf32(acc[mi][ni], ah[mi], bh);
                    }
                }
            } else {
                unsigned ah[MSUB][4];
                #pragma unroll
                for (int mi = 0; mi < MSUB; mi++) {
                    int mb = wm + mi*16;
                    ah[mi][0] = f2tf(Ab[(mb+gr  )*AKW + kb+tg  ]);
                    ah[mi][1] = f2tf(Ab[(mb+gr+8)*AKW + kb+tg  ]);
                    ah[mi][2] = f2tf(Ab[(mb+gr  )*AKW + kb+tg+4]);
                    ah[mi][3] = f2tf(Ab[(mb+gr+8)*AKW + kb+tg+4]);
                }
                #pragma unroll
                for (int ni = 0; ni < 8; ni++) {
                    int nb2 = wn + ni*8 + gr;
                    unsigned bh[2];
                    if (TRANSB) {
                        bh[0] = f2tf(Bb[nb2*AKW + kb+tg  ]);
                        bh[1] = f2tf(Bb[nb2*AKW + kb+tg+4]);
                    } else {
                        bh[0] = f2tf(Bb[(kb+tg  )*PADW + nb2]);
                        bh[1] = f2tf(Bb[(kb+tg+4)*PADW + nb2]);
                    }
                    #pragma unroll
                    for (int mi = 0; mi < MSUB; mi++)
                        mma_tf32(acc[mi][ni], ah[mi], bh);
                }
            }
        }
    }

    __syncthreads();
    // ---- epilogue ----
    #pragma unroll
    for (int mi = 0; mi < MSUB; mi++) {
        int r0 = m0 + wm + mi*16 + gr;
        #pragma unroll
        for (int ni = 0; ni < 8; ni++) {
            int c0 = n0 + wn + ni*8 + tg*2;
            float* p0 = &C[(size_t)r0*NPER + c0];
            float* p1 = &C[(size_t)(r0+8)*NPER + c0];
            if (ACC) {
                p0[0] += acc[mi][ni][0]; p0[1] += acc[mi][ni][1];
                p1[0] += acc[mi][ni][2]; p1[1] += acc[mi][ni][3];
            } else {
                p0[0] = acc[mi][ni][0]; p0[1] = acc[mi][ni][1];
                p1[0] = acc[mi][ni][2]; p1[1] = acc[mi][ni][3];
            }
        }
    }
}

#define GEMM_SMEM(MSUB)   ((3*((MSUB)*64*AKW) + 3*16*PADW) * 4)
#define GEMM_SMEM_T(MSUB) ((3*((MSUB)*64*AKW) + 3*128*AKW) * 4)

// ---------------- fused flash attention ----------------
#define ATTN_SMEM_BYTES ((3*64*65 + 64*64) * 4)

__global__ void __launch_bounds__(256)
attn_fused_kernel() {
    extern __shared__ float sm[];
    float (*Qs)[65] = (float(*)[65])sm;
    float (*Ks)[65] = (float(*)[65])(sm + 64*65);
    float (*Ps)[65] = (float(*)[65])(sm + 2*64*65);
    float (*Vs)[64] = (float(*)[64])(sm + 3*64*65);

    int bh = blockIdx.z;
    int b = bh >> 4, h = bh & 15;
    int it = blockIdx.y;
    int i0 = it << 6;
    int tid = threadIdx.x;
    int tx = tid & 15, ty = tid >> 4;

    #pragma unroll
    for (int e = 0; e < 16; e++) {
        int lin = tid + e*256;
        int r = lin >> 6, c = lin & 63;
        Qs[r][c] = g_q[(size_t)(b*SS + i0 + r)*DD + h*HD + c];
    }

    float m_run[4], l_run[4], o[4][4];
    #pragma unroll
    for (int i = 0; i < 4; i++) {
        m_run[i] = -1e30f; l_run[i] = 0.f;
        #pragma unroll
        for (int j = 0; j < 4; j++) o[i][j] = 0.f;
    }

    for (int jt = 0; jt <= it; jt++) {
        int j0 = jt << 6;
        #pragma unroll
        for (int e = 0; e < 16; e++) {
            int lin = tid + e*256;
            int r = lin >> 6, c = lin & 63;
            Ks[r][c] = g_k[(size_t)(b*SS + j0 + r)*DD + h*HD + c];
            Vs[r][c] = g_v[(size_t)(b*SS + j0 + r)*DD + h*HD + c];
        }
        __syncthreads();

        float s[4][4] = {};
        #pragma unroll 8
        for (int kk = 0; kk < 64; kk++) {
            float a[4], bb[4];
            #pragma unroll
            for (int i = 0; i < 4; i++) a[i]  = Qs[ty*4+i][kk];
            #pragma unroll
            for (int j = 0; j < 4; j++) bb[j] = Ks[tx*4+j][kk];
            #pragma unroll
            for (int i = 0; i < 4; i++)
                #pragma unroll
                for (int j = 0; j < 4; j++)
                    s[i][j] += a[i]*bb[j];
        }

        #pragma unroll
        for (int i = 0; i < 4; i++) {
            int gi = i0 + ty*4 + i;
            #pragma unroll
            for (int j = 0; j < 4; j++) {
                int gj = j0 + tx*4 + j;
                s[i][j] = (gj > gi) ? -1e30f : s[i][j]*0.125f;
            }
        }

        #pragma unroll
        for (int i = 0; i < 4; i++) {
            float mloc = fmaxf(fmaxf(s[i][0], s[i][1]), fmaxf(s[i][2], s[i][3]));
            #pragma unroll
            for (int off = 8; off > 0; off >>= 1)
                mloc = fmaxf(mloc, __shfl_xor_sync(0xffffffffu, mloc, off));
            float m_new = fmaxf(m_run[i], mloc);
            float corr = __expf(m_run[i] - m_new);
            l_run[i] *= corr;
            #pragma unroll
            for (int j = 0; j < 4; j++) o[i][j] *= corr;
            float rs = 0.f;
            #pragma unroll
            for (int j = 0; j < 4; j++) {
                s[i][j] = __expf(s[i][j] - m_new);
                rs += s[i][j];
            }
            #pragma unroll
            for (int off = 8; off > 0; off >>= 1)
                rs += __shfl_xor_sync(0xffffffffu, rs, off);
            l_run[i] += rs;
            m_run[i] = m_new;
        }

        #pragma unroll
        for (int i = 0; i < 4; i++)
            #pragma unroll
            for (int j = 0; j < 4; j++)
                Ps[ty*4+i][tx*4+j] = s[i][j];
        __syncthreads();

        #pragma unroll 8
        for (int kk = 0; kk < 64; kk++) {
            float a[4];
            #pragma unroll
            for (int i = 0; i < 4; i++) a[i] = Ps[ty*4+i][kk];
            float4 v4 = *(const float4*)&Vs[kk][tx*4];
            float bv[4] = {v4.x, v4.y, v4.z, v4.w};
            #pragma unroll
            for (int i = 0; i < 4; i++)
                #pragma unroll
                for (int j = 0; j < 4; j++)
                    o[i][j] += a[i]*bv[j];
        }
        __syncthreads();
    }

    #pragma unroll
    for (int i = 0; i < 4; i++) {
        float inv = 1.0f / l_run[i];
        #pragma unroll
        for (int j = 0; j < 4; j++)
            g_ao[(size_t)(b*SS + i0 + ty*4 + i)*DD + h*HD + tx*4 + j] = o[i][j]*inv;
    }
}

// ---------------- host launcher ----------------
extern "C" void kernel_launch(void* const* d_in, const int* in_sizes, int n_in,
                              void* d_out, int out_size) {
    const int*   tokens     = (const int*)  d_in[0];
    const float* emb        = (const float*)d_in[1];
    const float* wq         = (const float*)d_in[2];
    const float* wk         = (const float*)d_in[3];
    const float* wv         = (const float*)d_in[4];
    const float* wo         = (const float*)d_in[5];
    const float* w1         = (const float*)d_in[6];
    const float* w2         = (const float*)d_in[7];
    const float* w3         = (const float*)d_in[8];
    const float* attn_norm  = (const float*)d_in[9];
    const float* ffn_norm   = (const float*)d_in[10];
    const float* final_norm = (const float*)d_in[11];
    float* out = (float*)d_out;
    (void)in_sizes; (void)n_in; (void)out_size;

    float *p_h, *p_hn, *p_q, *p_k, *p_v, *p_ao, *p_f1, *p_f3;
    cudaGetSymbolAddress((void**)&p_h,  g_h);
    cudaGetSymbolAddress((void**)&p_hn, g_hn);
    cudaGetSymbolAddress((void**)&p_q,  g_q);
    cudaGetSymbolAddress((void**)&p_k,  g_k);
    cudaGetSymbolAddress((void**)&p_v,  g_v);
    cudaGetSymbolAddress((void**)&p_ao, g_ao);
    cudaGetSymbolAddress((void**)&p_f1, g_f1);
    cudaGetSymbolAddress((void**)&p_f3, g_f3);

    cudaFuncSetAttribute(attn_fused_kernel, cudaFuncAttributeMaxDynamicSharedMemorySize, ATTN_SMEM_BYTES);
    cudaFuncSetAttribute(gemm_tf32_fused<2,0,0,3>, cudaFuncAttributeMaxDynamicSharedMemorySize, GEMM_SMEM(2));
    cudaFuncSetAttribute(gemm_tf32_fused<1,1,0,3>, cudaFuncAttributeMaxDynamicSharedMemorySize, GEMM_SMEM(1));
    cudaFuncSetAttribute(gemm_tf32_fused<2,0,1,1>, cudaFuncAttributeMaxDynamicSharedMemorySize, GEMM_SMEM_T(2));

    rope_tables_kernel<<<(SS*(HD/2)+255)/256, 256>>>();
    embed_kernel<<<(MROWS*DD+255)/256, 256>>>(tokens, emb);

    for (int l = 0; l < LL; l++) {
        // attention block
        rmsnorm_kernel<<<MROWS, 256>>>(p_h, attn_norm + l*DD, p_hn);
        // fused QKV: 3 segments of N=DD -> grid 24 x 16 = 384 CTAs
        gemm_tf32_fused<2,0,0,3><<<dim3(3*(DD/128), MROWS/128), 256, GEMM_SMEM(2)>>>(
            p_hn, wq + (size_t)l*DD*DD, wk + (size_t)l*DD*DD, wv + (size_t)l*DD*DD,
            p_q, p_k, p_v, DD, DD);
        rope_kernel<<<(BB*SS*HH*(HD/2)+255)/256, 256>>>(p_q);
        rope_kernel<<<(BB*SS*HH*(HD/2)+255)/256, 256>>>(p_k);
        attn_fused_kernel<<<dim3(1, SS/64, BB*HH), 256, ATTN_SMEM_BYTES>>>();
        // WO (accumulate into h): 64-row tiles -> grid 8 x 32 = 256 CTAs
        gemm_tf32_fused<1,1,0,3><<<dim3(DD/128, MROWS/64), 256, GEMM_SMEM(1)>>>(
            p_ao, wo + (size_t)l*DD*DD, 0, 0, p_h, 0, 0, DD, DD);

        // FFN block
        rmsnorm_kernel<<<MROWS, 256>>>(p_h, ffn_norm + l*DD, p_hn);
        // fused W1+W3: 2 segments of N=FFD -> grid 44 x 16 = 704 CTAs
        gemm_tf32_fused<2,0,0,3><<<dim3(2*(FFD/128), MROWS/128), 256, GEMM_SMEM(2)>>>(
            p_hn, w1 + (size_t)l*DD*FFD, w3 + (size_t)l*DD*FFD, 0,
            p_f1, p_f3, 0, FFD, DD);
        silu_mul_kernel<<<(MROWS*FFD+255)/256, 256>>>();
        // W2 (accumulate into h): 64-row tiles -> grid 8 x 32 = 256 CTAs
        gemm_tf32_fused<1,1,0,3><<<dim3(DD/128, MROWS/64), 256, GEMM_SMEM(1)>>>(
            p_f1, w2 + (size_t)l*FFD*DD, 0, 0, p_h, 0, 0, DD, FFD);
    }

    rmsnorm_kernel<<<MROWS, 256>>>(p_h, final_norm, p_hn);
    // logits: C = hn @ emb^T, pure TF32 (rna), cp.async pipeline. grid 250 x 16 = 4000 CTAs
    gemm_tf32_fused<2,0,1,1><<<dim3(VV/128, MROWS/128), 256, GEMM_SMEM_T(2)>>>(
        p_hn, emb, 0, 0, out, 0, 0, VV, DD);
}